// round 4
// baseline (speedup 1.0000x reference)
#include <cuda_runtime.h>
#include <cuda_bf16.h>
#include <cstdint>

// Problem shapes (fixed for GCNNet_61323543052323)
#define NN   100000
#define FIN  512
#define HH   256
#define DOUT 128

// -------------------- scratch (device globals; referenced directly) -------
__device__ __align__(128) float g_deg [NN];
__device__ __align__(128) float g_dinv[NN];
__device__ __align__(128) float g_hs1 [(size_t)NN * HH];   // pre-scaled GEMM1 out; later reused as h1
__device__ __align__(128) float g_acc1[(size_t)NN * HH];
__device__ __align__(128) float g_hs2 [(size_t)NN * DOUT];
__device__ __align__(128) float g_acc2[(size_t)NN * DOUT];
__device__ int g_is64;   // 1 if edge_index is int64 on device, 0 if int32

// -------------------- edge dtype detection --------------------------------
// int64 edge data: every value < 2^17 -> int64 view valid.
// int32 edge data viewed as int64: a | (b<<32), b random in [0,1e5) -> invalid.
__global__ void k_detect(const void* __restrict__ ei_raw, int E) {
    const long long* p = (const long long*)ei_raw;
    int bad = 0;
    int n = (E < 1024) ? E : 1024;   // stays within buffer for both dtypes
    for (int j = threadIdx.x; j < n; j += 256) {
        long long v = p[j];
        if (v < 0 || v >= NN) bad = 1;
    }
    bad = __syncthreads_or(bad);
    if (threadIdx.x == 0) g_is64 = !bad;
}

// Safe edge-index accessor. which: 0 = src row, 1 = dst row.
__device__ __forceinline__ int edge_idx(const void* __restrict__ ei_raw,
                                        int E, int which, int e) {
    long long v;
    if (g_is64) v = ((const long long*)ei_raw)[(size_t)which * E + e];
    else        v = ((const int*)ei_raw)[(size_t)which * E + e];
    unsigned u = (unsigned)v;
    return (u < NN) ? (int)u : 0;    // clamp: never trap, worst case wrong value
}

// -------------------- degree / normalization ------------------------------
__global__ void k_deg_init() {
    int i = blockIdx.x * blockDim.x + threadIdx.x;
    if (i < NN) g_deg[i] = 1.0f;                     // self loop
}

__global__ void k_deg_count(const void* __restrict__ ei, int E) {
    int e = blockIdx.x * blockDim.x + threadIdx.x;
    if (e < E) atomicAdd(&g_deg[edge_idx(ei, E, 1, e)], 1.0f);
}

__global__ void k_dinv() {
    int i = blockIdx.x * blockDim.x + threadIdx.x;
    if (i < NN) g_dinv[i] = rsqrtf(g_deg[i]);        // deg >= 1 always
}

// -------------------- SGEMM: C = (A @ B) * dinv[row], written to C0 and C1 -
// LAYER 1: A = x (param),  B = W1, K=FIN, N=HH,   C0=g_hs1, C1=g_acc1
// LAYER 2: A = g_hs1,      B = W2, K=HH,  N=DOUT, C0=g_hs2, C1=g_acc2
template <int LAYER>
__global__ __launch_bounds__(256)
void sgemm_scale(const float* __restrict__ Ain, const float* __restrict__ B) {
    constexpr int K = (LAYER == 1) ? FIN : HH;
    constexpr int N = (LAYER == 1) ? HH  : DOUT;
    constexpr int M = NN;
    const float* __restrict__ A = (LAYER == 1) ? Ain : (const float*)g_hs1;
    float* __restrict__ C0 = (LAYER == 1) ? g_hs1  : g_hs2;
    float* __restrict__ C1 = (LAYER == 1) ? g_acc1 : g_acc2;

    const int BM = 128, BN = 128, BK = 8;
    __shared__ __align__(16) float As[BK][BM + 4];   // pad to kill store conflicts
    __shared__ __align__(16) float Bs[BK][BN];

    int tid = threadIdx.x;
    int tx  = tid & 15;          // column group (8 cols each)
    int ty  = tid >> 4;          // row group (8 rows each)
    int m0  = blockIdx.y * BM;
    int n0  = blockIdx.x * BN;

    float acc[8][8];
#pragma unroll
    for (int i = 0; i < 8; i++)
#pragma unroll
        for (int j = 0; j < 8; j++) acc[i][j] = 0.0f;

    for (int k0 = 0; k0 < K; k0 += BK) {
        // Load A tile (128x8) -> As[k][m]
#pragma unroll
        for (int l = 0; l < 4; l++) {
            int e = tid + l * 256;
            int m = e >> 3;            // /BK
            int k = e & 7;             // %BK
            int gm = m0 + m;
            float v = 0.0f;
            if (gm < M) v = A[(size_t)gm * K + k0 + k];
            As[k][m] = v;
        }
        // Load B tile (8x128) -> Bs[k][n]
#pragma unroll
        for (int l = 0; l < 4; l++) {
            int e = tid + l * 256;
            int k = e >> 7;            // /BN
            int n = e & 127;           // %BN
            Bs[k][n] = B[(size_t)(k0 + k) * N + n0 + n];
        }
        __syncthreads();

#pragma unroll
        for (int k = 0; k < BK; k++) {
            float4 a0 = *(const float4*)&As[k][ty * 8];
            float4 a1 = *(const float4*)&As[k][ty * 8 + 4];
            float4 b0 = *(const float4*)&Bs[k][tx * 8];
            float4 b1 = *(const float4*)&Bs[k][tx * 8 + 4];
            float a[8] = {a0.x, a0.y, a0.z, a0.w, a1.x, a1.y, a1.z, a1.w};
            float b[8] = {b0.x, b0.y, b0.z, b0.w, b1.x, b1.y, b1.z, b1.w};
#pragma unroll
            for (int i = 0; i < 8; i++)
#pragma unroll
                for (int j = 0; j < 8; j++)
                    acc[i][j] = fmaf(a[i], b[j], acc[i][j]);
        }
        __syncthreads();
    }

    // Epilogue: scale by dinv[row], write to both destinations (float4)
#pragma unroll
    for (int i = 0; i < 8; i++) {
        int gm = m0 + ty * 8 + i;
        if (gm >= M) continue;
        float s = g_dinv[gm];
        size_t base = (size_t)gm * N + n0 + tx * 8;
#pragma unroll
        for (int j = 0; j < 8; j += 4) {
            float4 v = make_float4(acc[i][j] * s, acc[i][j + 1] * s,
                                   acc[i][j + 2] * s, acc[i][j + 3] * s);
            *(float4*)&C0[base + j] = v;
            *(float4*)&C1[base + j] = v;
        }
    }
}

// -------------------- edge scatter: acc[dst] += hs[src] --------------------
// One thread handles one float4-chunk of one edge: vector gather (LDG.128),
// 4 scalar REDG.ADD.F32 to the destination row.
template <int LAYER>
__global__ void scatter_edges(const void* __restrict__ ei, int E) {
    constexpr int NC = (LAYER == 1) ? HH : DOUT;
    const float* __restrict__ hs  = (LAYER == 1) ? g_hs1  : g_hs2;
    float* __restrict__       acc = (LAYER == 1) ? g_acc1 : g_acc2;

    const int CH = NC / 4;                 // float4 chunks per edge row
    int gtid = blockIdx.x * blockDim.x + threadIdx.x;
    int e = gtid / CH;
    if (e >= E) return;
    int c = (gtid % CH) * 4;
    int src = edge_idx(ei, E, 0, e);
    int dst = edge_idx(ei, E, 1, e);
    float4 v = *(const float4*)&hs[(size_t)src * NC + c];
    float* p = &acc[(size_t)dst * NC + c];
    atomicAdd(p + 0, v.x);
    atomicAdd(p + 1, v.y);
    atomicAdd(p + 2, v.z);
    atomicAdd(p + 3, v.w);
}

// -------------------- post: out = act(acc * dinv[row] + bias) -------------
// LAYER 1: acc=g_acc1, out=g_hs1 (in place reuse), RELU
// LAYER 2: acc=g_acc2, out=d_out param, no RELU
template <int LAYER>
__global__ void post_bias(const float* __restrict__ bias, float* __restrict__ out_param) {
    constexpr int NC = (LAYER == 1) ? HH : DOUT;
    const float* __restrict__ acc = (LAYER == 1) ? g_acc1 : g_acc2;
    float* __restrict__ out = (LAYER == 1) ? g_hs1 : out_param;

    int i = blockIdx.x * blockDim.x + threadIdx.x;       // over rows*NC/4
    int total = NN * (NC / 4);
    if (i >= total) return;
    int r = i / (NC / 4);
    int c = (i % (NC / 4)) * 4;
    float s = g_dinv[r];
    float4 a = *(const float4*)&acc[(size_t)r * NC + c];
    float4 b = *(const float4*)&bias[c];
    float4 v = make_float4(fmaf(a.x, s, b.x), fmaf(a.y, s, b.y),
                           fmaf(a.z, s, b.z), fmaf(a.w, s, b.w));
    if (LAYER == 1) {
        v.x = fmaxf(v.x, 0.f); v.y = fmaxf(v.y, 0.f);
        v.z = fmaxf(v.z, 0.f); v.w = fmaxf(v.w, 0.f);
    }
    *(float4*)&out[(size_t)r * NC + c] = v;
}

// ---------------------------------------------------------------------------
extern "C" void kernel_launch(void* const* d_in, const int* in_sizes, int n_in,
                              void* d_out, int out_size) {
    const float* x  = (const float*)d_in[0];
    const void*  ei = d_in[1];                 // int32 or int64, detected on device
    const float* W1 = (const float*)d_in[2];
    const float* b1 = (const float*)d_in[3];
    const float* W2 = (const float*)d_in[4];
    const float* b2 = (const float*)d_in[5];
    float*       out = (float*)d_out;

    const int E = in_sizes[1] / 2;

    // 0. detect edge_index dtype
    k_detect<<<1, 256>>>(ei, E);

    // 1. degree + normalization
    k_deg_init <<<(NN + 255) / 256, 256>>>();
    k_deg_count<<<(E  + 255) / 256, 256>>>(ei, E);
    k_dinv     <<<(NN + 255) / 256, 256>>>();

    // 2. layer 1: hs1 = (x @ W1) * dinv[row]; acc1 initialized = hs1 (self loop)
    {
        dim3 grid(HH / 128, (NN + 127) / 128);
        sgemm_scale<1><<<grid, 256>>>(x, W1);
    }
    // 3. scatter: acc1[dst] += hs1[src]
    {
        long long work = (long long)E * (HH / 4);
        scatter_edges<1><<<(int)((work + 255) / 256), 256>>>(ei, E);
    }
    // 4. h1 = relu(acc1 * dinv + b1)  (written back into hs1 buffer)
    {
        int work = NN * (HH / 4);
        post_bias<1><<<(work + 255) / 256, 256>>>(b1, nullptr);
    }
    // 5. layer 2: hs2 = (h1 @ W2) * dinv[row]; acc2 = hs2
    {
        dim3 grid(DOUT / 128, (NN + 127) / 128);
        sgemm_scale<2><<<grid, 256>>>(nullptr, W2);
    }
    // 6. scatter: acc2[dst] += hs2[src]
    {
        long long work = (long long)E * (DOUT / 4);
        scatter_edges<2><<<(int)((work + 255) / 256), 256>>>(ei, E);
    }
    // 7. out = acc2 * dinv + b2
    {
        int work = NN * (DOUT / 4);
        post_bias<2><<<(work + 255) / 256, 256>>>(b2, out);
    }
}

// round 5
// speedup vs baseline: 1.0163x; 1.0163x over previous
#include <cuda_runtime.h>
#include <cuda_bf16.h>
#include <cstdint>

// Problem shapes (fixed for GCNNet_61323543052323)
#define NN   100000
#define FIN  512
#define HH   256
#define DOUT 128

// -------------------- scratch (device globals; referenced directly) -------
__device__ __align__(128) float g_deg [NN];
__device__ __align__(128) float g_dinv[NN];
__device__ __align__(128) float g_hs1 [(size_t)NN * HH];   // pre-scaled GEMM1 out; later reused as h1
__device__ __align__(128) float g_acc1[(size_t)NN * HH];
__device__ __align__(128) float g_hs2 [(size_t)NN * DOUT];
__device__ __align__(128) float g_acc2[(size_t)NN * DOUT];
__device__ int g_is64;   // 1 if edge_index is int64 on device, 0 if int32

// -------------------- edge dtype detection --------------------------------
__global__ void k_detect(const void* __restrict__ ei_raw, int E) {
    const long long* p = (const long long*)ei_raw;
    int bad = 0;
    int n = (E < 1024) ? E : 1024;
    for (int j = threadIdx.x; j < n; j += 256) {
        long long v = p[j];
        if (v < 0 || v >= NN) bad = 1;
    }
    bad = __syncthreads_or(bad);
    if (threadIdx.x == 0) g_is64 = !bad;
}

// Safe edge-index accessor. which: 0 = src row, 1 = dst row.
__device__ __forceinline__ int edge_idx(const void* __restrict__ ei_raw,
                                        int E, int which, int e) {
    long long v;
    if (g_is64) v = ((const long long*)ei_raw)[(size_t)which * E + e];
    else        v = ((const int*)ei_raw)[(size_t)which * E + e];
    unsigned u = (unsigned)v;
    return (u < NN) ? (int)u : 0;
}

// -------------------- degree / normalization ------------------------------
__global__ void k_deg_init() {
    int i = blockIdx.x * blockDim.x + threadIdx.x;
    if (i < NN) g_deg[i] = 1.0f;                     // self loop
}

__global__ void k_deg_count(const void* __restrict__ ei, int E) {
    int e = blockIdx.x * blockDim.x + threadIdx.x;
    if (e < E) atomicAdd(&g_deg[edge_idx(ei, E, 1, e)], 1.0f);
}

__global__ void k_dinv() {
    int i = blockIdx.x * blockDim.x + threadIdx.x;
    if (i < NN) g_dinv[i] = rsqrtf(g_deg[i]);        // deg >= 1 always
}

// -------------------- SGEMM: C = (A @ B) * dinv[row] -> C0 and C1 ---------
// Register-staged double-buffered pipeline: LDG next tile -> compute current
// tile from smem -> STS. BK=16, 128x128 block tile, 8x8 per thread.
template <int LAYER>
__global__ __launch_bounds__(256)
void sgemm_scale(const float* __restrict__ Ain, const float* __restrict__ B) {
    constexpr int K = (LAYER == 1) ? FIN : HH;
    constexpr int N = (LAYER == 1) ? HH  : DOUT;
    constexpr int M = NN;
    const float* __restrict__ A = (LAYER == 1) ? Ain : (const float*)g_hs1;
    float* __restrict__ C0 = (LAYER == 1) ? g_hs1  : g_hs2;
    float* __restrict__ C1 = (LAYER == 1) ? g_acc1 : g_acc2;

    constexpr int BM = 128, BN = 128, BK = 16;
    __shared__ __align__(16) float As[BK][BM + 4];   // [k][m], padded
    __shared__ __align__(16) float Bs[BK][BN];       // [k][n]

    const int tid = threadIdx.x;
    const int tx  = tid & 15;          // column group (8 cols each)
    const int ty  = tid >> 4;          // row group (8 rows each)
    const int m0  = blockIdx.y * BM;
    const int n0  = blockIdx.x * BN;

    // A-tile load mapping: 128 rows x 4 float4-chunks = 512 chunks, 2/thread
    const int a_row0 = (tid * 2) >> 2;          // chunk0 row
    const int a_c0   = (tid * 2) & 3;           // chunk0 col4
    const int a_row1 = (tid * 2 + 1) >> 2;
    const int a_c1   = (tid * 2 + 1) & 3;
    // B-tile load mapping: 16 rows x 32 float4-chunks = 512 chunks, 2/thread
    const int b_row0 = (tid * 2) >> 5;
    const int b_c0   = (tid * 2) & 31;
    const int b_row1 = (tid * 2 + 1) >> 5;
    const int b_c1   = (tid * 2 + 1) & 31;

    float4 ar0, ar1, br0, br1;

    auto ldg_tile = [&](int k0) {
        int gm0 = m0 + a_row0, gm1 = m0 + a_row1;
        ar0 = (gm0 < M) ? *(const float4*)&A[(size_t)gm0 * K + k0 + a_c0 * 4]
                        : make_float4(0.f, 0.f, 0.f, 0.f);
        ar1 = (gm1 < M) ? *(const float4*)&A[(size_t)gm1 * K + k0 + a_c1 * 4]
                        : make_float4(0.f, 0.f, 0.f, 0.f);
        br0 = *(const float4*)&B[(size_t)(k0 + b_row0) * N + n0 + b_c0 * 4];
        br1 = *(const float4*)&B[(size_t)(k0 + b_row1) * N + n0 + b_c1 * 4];
    };
    auto sts_tile = [&]() {
        As[a_c0 * 4 + 0][a_row0] = ar0.x;
        As[a_c0 * 4 + 1][a_row0] = ar0.y;
        As[a_c0 * 4 + 2][a_row0] = ar0.z;
        As[a_c0 * 4 + 3][a_row0] = ar0.w;
        As[a_c1 * 4 + 0][a_row1] = ar1.x;
        As[a_c1 * 4 + 1][a_row1] = ar1.y;
        As[a_c1 * 4 + 2][a_row1] = ar1.z;
        As[a_c1 * 4 + 3][a_row1] = ar1.w;
        *(float4*)&Bs[b_row0][b_c0 * 4] = br0;
        *(float4*)&Bs[b_row1][b_c1 * 4] = br1;
    };

    float acc[8][8];
#pragma unroll
    for (int i = 0; i < 8; i++)
#pragma unroll
        for (int j = 0; j < 8; j++) acc[i][j] = 0.0f;

    auto compute_tile = [&]() {
#pragma unroll
        for (int k = 0; k < BK; k++) {
            float4 a0 = *(const float4*)&As[k][ty * 8];
            float4 a1 = *(const float4*)&As[k][ty * 8 + 4];
            float4 b0 = *(const float4*)&Bs[k][tx * 8];
            float4 b1 = *(const float4*)&Bs[k][tx * 8 + 4];
            float a[8] = {a0.x, a0.y, a0.z, a0.w, a1.x, a1.y, a1.z, a1.w};
            float b[8] = {b0.x, b0.y, b0.z, b0.w, b1.x, b1.y, b1.z, b1.w};
#pragma unroll
            for (int i = 0; i < 8; i++)
#pragma unroll
                for (int j = 0; j < 8; j++)
                    acc[i][j] = fmaf(a[i], b[j], acc[i][j]);
        }
    };

    // prologue
    ldg_tile(0);
    sts_tile();
    __syncthreads();

    for (int k0 = BK; k0 < K; k0 += BK) {
        ldg_tile(k0);          // prefetch next tile into registers
        compute_tile();        // compute current tile from smem
        __syncthreads();       // all reads of smem done
        sts_tile();            // stage next tile
        __syncthreads();       // next tile visible
    }
    compute_tile();            // last tile

    // Epilogue: scale by dinv[row], write to both destinations (float4)
#pragma unroll
    for (int i = 0; i < 8; i++) {
        int gm = m0 + ty * 8 + i;
        if (gm >= M) continue;
        float s = g_dinv[gm];
        size_t base = (size_t)gm * N + n0 + tx * 8;
#pragma unroll
        for (int j = 0; j < 8; j += 4) {
            float4 v = make_float4(acc[i][j] * s, acc[i][j + 1] * s,
                                   acc[i][j + 2] * s, acc[i][j + 3] * s);
            *(float4*)&C0[base + j] = v;
            *(float4*)&C1[base + j] = v;
        }
    }
}

// -------------------- edge scatter: acc[dst] += hs[src] --------------------
template <int LAYER>
__global__ void scatter_edges(const void* __restrict__ ei, int E) {
    constexpr int NC = (LAYER == 1) ? HH : DOUT;
    const float* __restrict__ hs  = (LAYER == 1) ? g_hs1  : g_hs2;
    float* __restrict__       acc = (LAYER == 1) ? g_acc1 : g_acc2;

    const int CH = NC / 4;                 // float4 chunks per edge row
    int gtid = blockIdx.x * blockDim.x + threadIdx.x;
    int e = gtid / CH;
    if (e >= E) return;
    int c = (gtid % CH) * 4;
    int src = edge_idx(ei, E, 0, e);
    int dst = edge_idx(ei, E, 1, e);
    float4 v = *(const float4*)&hs[(size_t)src * NC + c];
    float* p = &acc[(size_t)dst * NC + c];
    atomicAdd(p + 0, v.x);
    atomicAdd(p + 1, v.y);
    atomicAdd(p + 2, v.z);
    atomicAdd(p + 3, v.w);
}

// -------------------- post: out = act(acc * dinv[row] + bias) -------------
template <int LAYER>
__global__ void post_bias(const float* __restrict__ bias, float* __restrict__ out_param) {
    constexpr int NC = (LAYER == 1) ? HH : DOUT;
    const float* __restrict__ acc = (LAYER == 1) ? g_acc1 : g_acc2;
    float* __restrict__ out = (LAYER == 1) ? g_hs1 : out_param;

    int i = blockIdx.x * blockDim.x + threadIdx.x;       // over rows*NC/4
    int total = NN * (NC / 4);
    if (i >= total) return;
    int r = i / (NC / 4);
    int c = (i % (NC / 4)) * 4;
    float s = g_dinv[r];
    float4 a = *(const float4*)&acc[(size_t)r * NC + c];
    float4 b = *(const float4*)&bias[c];
    float4 v = make_float4(fmaf(a.x, s, b.x), fmaf(a.y, s, b.y),
                           fmaf(a.z, s, b.z), fmaf(a.w, s, b.w));
    if (LAYER == 1) {
        v.x = fmaxf(v.x, 0.f); v.y = fmaxf(v.y, 0.f);
        v.z = fmaxf(v.z, 0.f); v.w = fmaxf(v.w, 0.f);
    }
    *(float4*)&out[(size_t)r * NC + c] = v;
}

// ---------------------------------------------------------------------------
extern "C" void kernel_launch(void* const* d_in, const int* in_sizes, int n_in,
                              void* d_out, int out_size) {
    const float* x  = (const float*)d_in[0];
    const void*  ei = d_in[1];                 // int32 or int64, detected on device
    const float* W1 = (const float*)d_in[2];
    const float* b1 = (const float*)d_in[3];
    const float* W2 = (const float*)d_in[4];
    const float* b2 = (const float*)d_in[5];
    float*       out = (float*)d_out;

    const int E = in_sizes[1] / 2;

    // 0. detect edge_index dtype
    k_detect<<<1, 256>>>(ei, E);

    // 1. degree + normalization
    k_deg_init <<<(NN + 255) / 256, 256>>>();
    k_deg_count<<<(E  + 255) / 256, 256>>>(ei, E);
    k_dinv     <<<(NN + 255) / 256, 256>>>();

    // 2. layer 1: hs1 = (x @ W1) * dinv[row]; acc1 initialized = hs1 (self loop)
    {
        dim3 grid(HH / 128, (NN + 127) / 128);
        sgemm_scale<1><<<grid, 256>>>(x, W1);
    }
    // 3. scatter: acc1[dst] += hs1[src]
    {
        long long work = (long long)E * (HH / 4);
        scatter_edges<1><<<(int)((work + 255) / 256), 256>>>(ei, E);
    }
    // 4. h1 = relu(acc1 * dinv + b1)  (written back into hs1 buffer)
    {
        int work = NN * (HH / 4);
        post_bias<1><<<(work + 255) / 256, 256>>>(b1, nullptr);
    }
    // 5. layer 2: hs2 = (h1 @ W2) * dinv[row]; acc2 = hs2
    {
        dim3 grid(DOUT / 128, (NN + 127) / 128);
        sgemm_scale<2><<<grid, 256>>>(nullptr, W2);
    }
    // 6. scatter: acc2[dst] += hs2[src]
    {
        long long work = (long long)E * (DOUT / 4);
        scatter_edges<2><<<(int)((work + 255) / 256), 256>>>(ei, E);
    }
    // 7. out = acc2 * dinv + b2
    {
        int work = NN * (DOUT / 4);
        post_bias<2><<<(work + 255) / 256, 256>>>(b2, out);
    }
}

// round 8
// speedup vs baseline: 1.3599x; 1.3381x over previous
#include <cuda_runtime.h>
#include <cuda_bf16.h>
#include <cstdint>

// Problem shapes (fixed for GCNNet_61323543052323)
#define NN   100000
#define FIN  512
#define HH   256
#define DOUT 128

// -------------------- scratch (device globals; referenced directly) -------
__device__ __align__(128) float g_deg [NN];
__device__ __align__(128) float g_dinv[NN];
__device__ __align__(128) float g_hs1 [(size_t)NN * HH];
__device__ __align__(128) float g_acc1[(size_t)NN * HH];
__device__ __align__(128) float g_hs2 [(size_t)NN * DOUT];
__device__ __align__(128) float g_acc2[(size_t)NN * DOUT];
__device__ __align__(128) __nv_bfloat16 g_h1h[(size_t)NN * HH];   // h1 split hi
__device__ __align__(128) __nv_bfloat16 g_h1l[(size_t)NN * HH];   // h1 split lo
__device__ __align__(128) __nv_bfloat16 g_w1th[(size_t)HH * FIN]; // W1^T hi [N][K]
__device__ __align__(128) __nv_bfloat16 g_w1tl[(size_t)HH * FIN];
__device__ __align__(128) __nv_bfloat16 g_w2th[(size_t)DOUT * HH];
__device__ __align__(128) __nv_bfloat16 g_w2tl[(size_t)DOUT * HH];
__device__ int g_is64;

// -------------------- helpers ----------------------------------------------
__device__ __forceinline__ uint32_t smem_u32(const void* p) {
    uint32_t a;
    asm("{ .reg .u64 t; cvta.to.shared.u64 t, %1; cvt.u32.u64 %0, t; }" : "=r"(a) : "l"(p));
    return a;
}
__device__ __forceinline__ void ldmx4(uint32_t* r, uint32_t addr) {
    asm volatile("ldmatrix.sync.aligned.m8n8.x4.shared.b16 {%0,%1,%2,%3}, [%4];"
                 : "=r"(r[0]), "=r"(r[1]), "=r"(r[2]), "=r"(r[3]) : "r"(addr));
}
__device__ __forceinline__ void mma_bf16(float* d, const uint32_t* a, const uint32_t* b) {
    asm volatile(
        "mma.sync.aligned.m16n8k16.row.col.f32.bf16.bf16.f32 "
        "{%0,%1,%2,%3}, {%4,%5,%6,%7}, {%8,%9}, {%0,%1,%2,%3};"
        : "+f"(d[0]), "+f"(d[1]), "+f"(d[2]), "+f"(d[3])
        : "r"(a[0]), "r"(a[1]), "r"(a[2]), "r"(a[3]), "r"(b[0]), "r"(b[1]));
}
__device__ __forceinline__ void split_bf16(float v, unsigned short& h, unsigned short& l) {
    __nv_bfloat16 bh = __float2bfloat16_rn(v);
    float r = v - __bfloat162float(bh);
    h = __bfloat16_as_ushort(bh);
    l = __bfloat16_as_ushort(__float2bfloat16_rn(r));
}
// split 8 floats (2 float4) -> hi uint4, lo uint4
__device__ __forceinline__ void split8(const float4& f0, const float4& f1, uint4& H, uint4& L) {
    unsigned short h[8], l[8];
    split_bf16(f0.x, h[0], l[0]); split_bf16(f0.y, h[1], l[1]);
    split_bf16(f0.z, h[2], l[2]); split_bf16(f0.w, h[3], l[3]);
    split_bf16(f1.x, h[4], l[4]); split_bf16(f1.y, h[5], l[5]);
    split_bf16(f1.z, h[6], l[6]); split_bf16(f1.w, h[7], l[7]);
    H = make_uint4((uint32_t)h[0] | ((uint32_t)h[1] << 16), (uint32_t)h[2] | ((uint32_t)h[3] << 16),
                   (uint32_t)h[4] | ((uint32_t)h[5] << 16), (uint32_t)h[6] | ((uint32_t)h[7] << 16));
    L = make_uint4((uint32_t)l[0] | ((uint32_t)l[1] << 16), (uint32_t)l[2] | ((uint32_t)l[3] << 16),
                   (uint32_t)l[4] | ((uint32_t)l[5] << 16), (uint32_t)l[6] | ((uint32_t)l[7] << 16));
}

// -------------------- edge dtype detection --------------------------------
__global__ void k_detect(const void* __restrict__ ei_raw, int E) {
    const long long* p = (const long long*)ei_raw;
    int bad = 0;
    int n = (E < 1024) ? E : 1024;
    for (int j = threadIdx.x; j < n; j += 256) {
        long long v = p[j];
        if (v < 0 || v >= NN) bad = 1;
    }
    bad = __syncthreads_or(bad);
    if (threadIdx.x == 0) g_is64 = !bad;
}
__device__ __forceinline__ int edge_idx(const void* __restrict__ ei_raw,
                                        int E, int which, int e) {
    long long v;
    if (g_is64) v = ((const long long*)ei_raw)[(size_t)which * E + e];
    else        v = ((const int*)ei_raw)[(size_t)which * E + e];
    unsigned u = (unsigned)v;
    return (u < NN) ? (int)u : 0;
}

// -------------------- degree / normalization ------------------------------
__global__ void k_deg_init() {
    int i = blockIdx.x * blockDim.x + threadIdx.x;
    if (i < NN) g_deg[i] = 1.0f;
}
__global__ void k_deg_count(const void* __restrict__ ei, int E) {
    int e = blockIdx.x * blockDim.x + threadIdx.x;
    if (e < E) atomicAdd(&g_deg[edge_idx(ei, E, 1, e)], 1.0f);
}
__global__ void k_dinv() {
    int i = blockIdx.x * blockDim.x + threadIdx.x;
    if (i < NN) g_dinv[i] = rsqrtf(g_deg[i]);
}

// -------------------- W transpose + bf16 split: W[K,N] -> Wt[N,K] hi/lo ----
// Output arrays selected INSIDE device code (host must not name __device__ vars).
template <int LAYER>
__global__ void k_wsplit(const float* __restrict__ W) {
    constexpr int K = (LAYER == 1) ? FIN : HH;
    constexpr int N = (LAYER == 1) ? HH  : DOUT;
    __nv_bfloat16* __restrict__ oh = (LAYER == 1) ? g_w1th : g_w2th;
    __nv_bfloat16* __restrict__ ol = (LAYER == 1) ? g_w1tl : g_w2tl;
    int idx = blockIdx.x * blockDim.x + threadIdx.x;
    if (idx >= K * N) return;
    int k = idx / N, n = idx % N;
    unsigned short h, l;
    split_bf16(W[idx], h, l);
    oh[(size_t)n * K + k] = __ushort_as_bfloat16(h);
    ol[(size_t)n * K + k] = __ushort_as_bfloat16(l);
}

// -------------------- bf16 split-3 GEMM via mma.sync (HMMA) ----------------
// C = (A @ W) * dinv[row] -> C0 and C1.  Block 128x128xBK32, 8 warps (4m x 2n),
// warp tile 32x64.  D = Ah@Bh + Al@Bh + Ah@Bl, fp32 accum.
template <int LAYER>
__global__ __launch_bounds__(256, 1)
void k_gemm_mma(const float* __restrict__ x) {
    constexpr int K  = (LAYER == 1) ? FIN : HH;
    constexpr int N  = (LAYER == 1) ? HH  : DOUT;
    constexpr int M  = NN;
    constexpr int BK = 32;
    constexpr int NIT = K / BK;
    constexpr int ASTR = 80;                 // bytes per smem row (40 bf16, pad 8)
    constexpr int AH = 0, AL = 10240, BHo = 20480, BLo = 30720;

    extern __shared__ char smem[];
    const uint32_t sb = smem_u32(smem);

    const __nv_bfloat16* __restrict__ Wth = (LAYER == 1) ? g_w1th : g_w2th;
    const __nv_bfloat16* __restrict__ Wtl = (LAYER == 1) ? g_w1tl : g_w2tl;
    float* __restrict__ C0 = (LAYER == 1) ? g_hs1  : g_hs2;
    float* __restrict__ C1 = (LAYER == 1) ? g_acc1 : g_acc2;

    const int tid  = threadIdx.x;
    const int lane = tid & 31;
    const int wid  = tid >> 5;
    const int wm   = (wid & 3) * 32;
    const int wn   = (wid >> 2) * 64;
    const int m0   = blockIdx.y * 128;
    const int n0   = blockIdx.x * 128;

    const int a_rs = (lane & 7) + ((lane >> 3) & 1) * 8;
    const int a_ch = lane >> 4;
    uint32_t a_base[2];
#pragma unroll
    for (int mt = 0; mt < 2; mt++)
        a_base[mt] = sb + AH + (uint32_t)(wm + mt * 16 + a_rs) * ASTR + a_ch * 16;
    const int b_row = (lane & 7) + (lane >> 4) * 8;
    const int b_ch  = (lane >> 3) & 1;
    uint32_t b_base[4];
#pragma unroll
    for (int p = 0; p < 4; p++)
        b_base[p] = sb + BHo + (uint32_t)(wn + p * 16 + b_row) * ASTR + b_ch * 16;

    float acc[2][8][4];
#pragma unroll
    for (int i = 0; i < 2; i++)
#pragma unroll
        for (int j = 0; j < 8; j++)
#pragma unroll
            for (int q = 0; q < 4; q++) acc[i][j][q] = 0.0f;

    float4 fa[4];
    uint4 vah[2], val[2], vbh[2], vbl[2];

    auto ldg = [&](int it) {
        const int k0 = it * BK;
#pragma unroll
        for (int s = 0; s < 2; s++) {
            int lin = s * 256 + tid;
            int row = lin >> 2, c4 = lin & 3;
            int gm = m0 + row;
            if constexpr (LAYER == 1) {
                if (gm < M) {
                    fa[s * 2]     = *(const float4*)&x[(size_t)gm * K + k0 + c4 * 8];
                    fa[s * 2 + 1] = *(const float4*)&x[(size_t)gm * K + k0 + c4 * 8 + 4];
                } else {
                    fa[s * 2] = fa[s * 2 + 1] = make_float4(0.f, 0.f, 0.f, 0.f);
                }
            } else {
                if (gm < M) {
                    vah[s] = *(const uint4*)((const unsigned short*)g_h1h + (size_t)gm * K + k0 + c4 * 8);
                    val[s] = *(const uint4*)((const unsigned short*)g_h1l + (size_t)gm * K + k0 + c4 * 8);
                } else {
                    vah[s] = val[s] = make_uint4(0, 0, 0, 0);
                }
            }
            vbh[s] = *(const uint4*)((const unsigned short*)Wth + (size_t)(n0 + row) * K + k0 + c4 * 8);
            vbl[s] = *(const uint4*)((const unsigned short*)Wtl + (size_t)(n0 + row) * K + k0 + c4 * 8);
        }
    };

    auto sts = [&]() {
#pragma unroll
        for (int s = 0; s < 2; s++) {
            int lin = s * 256 + tid;
            int row = lin >> 2, c4 = lin & 3;
            uint32_t off = (uint32_t)row * ASTR + c4 * 16;
            if constexpr (LAYER == 1) {
                uint4 H, L;
                split8(fa[s * 2], fa[s * 2 + 1], H, L);
                *(uint4*)(smem + AH + off) = H;
                *(uint4*)(smem + AL + off) = L;
            } else {
                *(uint4*)(smem + AH + off) = vah[s];
                *(uint4*)(smem + AL + off) = val[s];
            }
            *(uint4*)(smem + BHo + off) = vbh[s];
            *(uint4*)(smem + BLo + off) = vbl[s];
        }
    };

    auto compute = [&]() {
#pragma unroll
        for (int ks = 0; ks < 2; ks++) {
            uint32_t ah[2][4], al[2][4], bf[8][2];
            ldmx4(ah[0], a_base[0] + ks * 32);
            ldmx4(ah[1], a_base[1] + ks * 32);
            ldmx4(al[0], a_base[0] + (AL - AH) + ks * 32);
            ldmx4(al[1], a_base[1] + (AL - AH) + ks * 32);
#pragma unroll
            for (int p = 0; p < 4; p++) {
                uint32_t r[4];
                ldmx4(r, b_base[p] + ks * 32);
                bf[2 * p][0] = r[0]; bf[2 * p][1] = r[1];
                bf[2 * p + 1][0] = r[2]; bf[2 * p + 1][1] = r[3];
            }
#pragma unroll
            for (int mt = 0; mt < 2; mt++)
#pragma unroll
                for (int nt = 0; nt < 8; nt++) mma_bf16(acc[mt][nt], ah[mt], bf[nt]);
#pragma unroll
            for (int mt = 0; mt < 2; mt++)
#pragma unroll
                for (int nt = 0; nt < 8; nt++) mma_bf16(acc[mt][nt], al[mt], bf[nt]);
#pragma unroll
            for (int p = 0; p < 4; p++) {
                uint32_t r[4];
                ldmx4(r, b_base[p] + (BLo - BHo) + ks * 32);
                bf[2 * p][0] = r[0]; bf[2 * p][1] = r[1];
                bf[2 * p + 1][0] = r[2]; bf[2 * p + 1][1] = r[3];
            }
#pragma unroll
            for (int mt = 0; mt < 2; mt++)
#pragma unroll
                for (int nt = 0; nt < 8; nt++) mma_bf16(acc[mt][nt], ah[mt], bf[nt]);
        }
    };

    ldg(0);
    sts();
    __syncthreads();
    for (int it = 1; it < NIT; it++) {
        ldg(it);
        compute();
        __syncthreads();
        sts();
        __syncthreads();
    }
    compute();
    __syncthreads();

    // epilogue: acc -> smem [128][132] fp32 -> scaled coalesced stores
    float* Ds = (float*)smem;
#pragma unroll
    for (int mt = 0; mt < 2; mt++)
#pragma unroll
        for (int nt = 0; nt < 8; nt++) {
            int r0 = wm + mt * 16 + (lane >> 2);
            int col = wn + nt * 8 + (lane & 3) * 2;
            Ds[r0 * 132 + col]           = acc[mt][nt][0];
            Ds[r0 * 132 + col + 1]       = acc[mt][nt][1];
            Ds[(r0 + 8) * 132 + col]     = acc[mt][nt][2];
            Ds[(r0 + 8) * 132 + col + 1] = acc[mt][nt][3];
        }
    __syncthreads();
#pragma unroll
    for (int i = 0; i < 16; i++) {
        int row = i * 8 + wid;
        int gm = m0 + row;
        if (gm < M) {
            float s = g_dinv[gm];
            float4 v = *(float4*)&Ds[row * 132 + lane * 4];
            v.x *= s; v.y *= s; v.z *= s; v.w *= s;
            size_t off = (size_t)gm * N + n0 + lane * 4;
            *(float4*)&C0[off] = v;
            *(float4*)&C1[off] = v;
        }
    }
}

// -------------------- edge scatter: acc[dst] += hs[src] --------------------
template <int LAYER>
__global__ void scatter_edges(const void* __restrict__ ei, int E) {
    constexpr int NC = (LAYER == 1) ? HH : DOUT;
    const float* __restrict__ hs  = (LAYER == 1) ? g_hs1  : g_hs2;
    float* __restrict__       acc = (LAYER == 1) ? g_acc1 : g_acc2;

    const int CH = NC / 4;
    int gtid = blockIdx.x * blockDim.x + threadIdx.x;
    int e = gtid / CH;
    if (e >= E) return;
    int c = (gtid % CH) * 4;
    int src = edge_idx(ei, E, 0, e);
    int dst = edge_idx(ei, E, 1, e);
    float4 v = *(const float4*)&hs[(size_t)src * NC + c];
    float* p = &acc[(size_t)dst * NC + c];
    atomicAdd(p + 0, v.x);
    atomicAdd(p + 1, v.y);
    atomicAdd(p + 2, v.z);
    atomicAdd(p + 3, v.w);
}

// -------------------- post: out = act(acc * dinv[row] + bias) -------------
template <int LAYER>
__global__ void post_bias(const float* __restrict__ bias, float* __restrict__ out_param) {
    constexpr int NC = (LAYER == 1) ? HH : DOUT;
    const float* __restrict__ acc = (LAYER == 1) ? g_acc1 : g_acc2;

    int i = blockIdx.x * blockDim.x + threadIdx.x;
    int total = NN * (NC / 4);
    if (i >= total) return;
    int r = i / (NC / 4);
    int c = (i % (NC / 4)) * 4;
    float s = g_dinv[r];
    float4 a = *(const float4*)&acc[(size_t)r * NC + c];
    float4 b = *(const float4*)&bias[c];
    float4 v = make_float4(fmaf(a.x, s, b.x), fmaf(a.y, s, b.y),
                           fmaf(a.z, s, b.z), fmaf(a.w, s, b.w));
    if (LAYER == 1) {
        v.x = fmaxf(v.x, 0.f); v.y = fmaxf(v.y, 0.f);
        v.z = fmaxf(v.z, 0.f); v.w = fmaxf(v.w, 0.f);
        unsigned short h0, h1, h2, h3, l0, l1, l2, l3;
        split_bf16(v.x, h0, l0); split_bf16(v.y, h1, l1);
        split_bf16(v.z, h2, l2); split_bf16(v.w, h3, l3);
        uint2 uh = make_uint2((uint32_t)h0 | ((uint32_t)h1 << 16),
                              (uint32_t)h2 | ((uint32_t)h3 << 16));
        uint2 ul = make_uint2((uint32_t)l0 | ((uint32_t)l1 << 16),
                              (uint32_t)l2 | ((uint32_t)l3 << 16));
        *(uint2*)((unsigned short*)g_h1h + (size_t)r * NC + c) = uh;
        *(uint2*)((unsigned short*)g_h1l + (size_t)r * NC + c) = ul;
        return;  // h1 only consumed as bf16 splits by layer-2 GEMM
    }
    *(float4*)&out_param[(size_t)r * NC + c] = v;
}

// ---------------------------------------------------------------------------
extern "C" void kernel_launch(void* const* d_in, const int* in_sizes, int n_in,
                              void* d_out, int out_size) {
    const float* x  = (const float*)d_in[0];
    const void*  ei = d_in[1];
    const float* W1 = (const float*)d_in[2];
    const float* b1 = (const float*)d_in[3];
    const float* W2 = (const float*)d_in[4];
    const float* b2 = (const float*)d_in[5];
    float*       out = (float*)d_out;

    const int E = in_sizes[1] / 2;
    const int MB = (NN + 127) / 128;          // 782
    const int SMEM = 128 * 132 * 4;           // 67584 (epilogue bound > 40960 mainloop)

    cudaFuncSetAttribute(k_gemm_mma<1>, cudaFuncAttributeMaxDynamicSharedMemorySize, SMEM);
    cudaFuncSetAttribute(k_gemm_mma<2>, cudaFuncAttributeMaxDynamicSharedMemorySize, SMEM);

    // 0. edge dtype + degrees + W preprocessing
    k_detect<<<1, 256>>>(ei, E);
    k_deg_init <<<(NN + 255) / 256, 256>>>();
    k_deg_count<<<(E  + 255) / 256, 256>>>(ei, E);
    k_dinv     <<<(NN + 255) / 256, 256>>>();
    k_wsplit<1><<<(FIN * HH + 255) / 256, 256>>>(W1);
    k_wsplit<2><<<(HH * DOUT + 255) / 256, 256>>>(W2);

    // layer 1: hs1 = (x @ W1) * dinv[row]; acc1 = hs1 (self loop)
    k_gemm_mma<1><<<dim3(HH / 128, MB), 256, SMEM>>>(x);
    {
        long long work = (long long)E * (HH / 4);
        scatter_edges<1><<<(int)((work + 255) / 256), 256>>>(ei, E);
    }
    {
        int work = NN * (HH / 4);
        post_bias<1><<<(work + 255) / 256, 256>>>(b1, nullptr);
    }
    // layer 2: hs2 = (h1 @ W2) * dinv[row]; acc2 = hs2
    k_gemm_mma<2><<<dim3(DOUT / 128, MB), 256, SMEM>>>(nullptr);
    {
        long long work = (long long)E * (DOUT / 4);
        scatter_edges<2><<<(int)((work + 255) / 256), 256>>>(ei, E);
    }
    {
        int work = NN * (DOUT / 4);
        post_bias<2><<<(work + 255) / 256, 256>>>(b2, out);
    }
}

// round 9
// speedup vs baseline: 2.9614x; 2.1776x over previous
#include <cuda_runtime.h>
#include <cuda_bf16.h>
#include <cstdint>

// Problem shapes (fixed for GCNNet_61323543052323)
#define NN   100000
#define FIN  512
#define HH   256
#define DOUT 128
#define EMAX 800000
#define NBLK ((NN + 255) / 256)

// -------------------- scratch (device globals) ------------------------------
__device__ __align__(128) float g_dinv[NN];
__device__ __align__(128) float g_hs1 [(size_t)NN * HH];
__device__ __align__(128) float g_hs2 [(size_t)NN * DOUT];
__device__ __align__(128) __nv_bfloat16 g_h1h[(size_t)NN * HH];
__device__ __align__(128) __nv_bfloat16 g_h1l[(size_t)NN * HH];
__device__ __align__(128) __nv_bfloat16 g_w1th[(size_t)HH * FIN]; // W1^T hi [N][K]
__device__ __align__(128) __nv_bfloat16 g_w1tl[(size_t)HH * FIN];
__device__ __align__(128) __nv_bfloat16 g_w2th[(size_t)DOUT * HH];
__device__ __align__(128) __nv_bfloat16 g_w2tl[(size_t)DOUT * HH];
// CSR by destination
__device__ __align__(128) int g_cnt [NN];
__device__ __align__(128) int g_fill[NN];
__device__ __align__(128) int g_ptr [NN + 1];
__device__ __align__(128) int g_part[NBLK];
__device__ __align__(128) int g_poff[NBLK];
__device__ __align__(128) int g_csr [EMAX];
__device__ int g_is64;

// -------------------- helpers ----------------------------------------------
__device__ __forceinline__ uint32_t smem_u32(const void* p) {
    uint32_t a;
    asm("{ .reg .u64 t; cvta.to.shared.u64 t, %1; cvt.u32.u64 %0, t; }" : "=r"(a) : "l"(p));
    return a;
}
__device__ __forceinline__ void ldmx4(uint32_t* r, uint32_t addr) {
    asm volatile("ldmatrix.sync.aligned.m8n8.x4.shared.b16 {%0,%1,%2,%3}, [%4];"
                 : "=r"(r[0]), "=r"(r[1]), "=r"(r[2]), "=r"(r[3]) : "r"(addr));
}
__device__ __forceinline__ void mma_bf16(float* d, const uint32_t* a, const uint32_t* b) {
    asm volatile(
        "mma.sync.aligned.m16n8k16.row.col.f32.bf16.bf16.f32 "
        "{%0,%1,%2,%3}, {%4,%5,%6,%7}, {%8,%9}, {%0,%1,%2,%3};"
        : "+f"(d[0]), "+f"(d[1]), "+f"(d[2]), "+f"(d[3])
        : "r"(a[0]), "r"(a[1]), "r"(a[2]), "r"(a[3]), "r"(b[0]), "r"(b[1]));
}
__device__ __forceinline__ void split_bf16(float v, unsigned short& h, unsigned short& l) {
    __nv_bfloat16 bh = __float2bfloat16_rn(v);
    float r = v - __bfloat162float(bh);
    h = __bfloat16_as_ushort(bh);
    l = __bfloat16_as_ushort(__float2bfloat16_rn(r));
}
__device__ __forceinline__ void split8(const float4& f0, const float4& f1, uint4& H, uint4& L) {
    unsigned short h[8], l[8];
    split_bf16(f0.x, h[0], l[0]); split_bf16(f0.y, h[1], l[1]);
    split_bf16(f0.z, h[2], l[2]); split_bf16(f0.w, h[3], l[3]);
    split_bf16(f1.x, h[4], l[4]); split_bf16(f1.y, h[5], l[5]);
    split_bf16(f1.z, h[6], l[6]); split_bf16(f1.w, h[7], l[7]);
    H = make_uint4((uint32_t)h[0] | ((uint32_t)h[1] << 16), (uint32_t)h[2] | ((uint32_t)h[3] << 16),
                   (uint32_t)h[4] | ((uint32_t)h[5] << 16), (uint32_t)h[6] | ((uint32_t)h[7] << 16));
    L = make_uint4((uint32_t)l[0] | ((uint32_t)l[1] << 16), (uint32_t)l[2] | ((uint32_t)l[3] << 16),
                   (uint32_t)l[4] | ((uint32_t)l[5] << 16), (uint32_t)l[6] | ((uint32_t)l[7] << 16));
}

// -------------------- edge dtype detection --------------------------------
__global__ void k_detect(const void* __restrict__ ei_raw, int E) {
    const long long* p = (const long long*)ei_raw;
    int bad = 0;
    int n = (E < 1024) ? E : 1024;
    for (int j = threadIdx.x; j < n; j += 256) {
        long long v = p[j];
        if (v < 0 || v >= NN) bad = 1;
    }
    bad = __syncthreads_or(bad);
    if (threadIdx.x == 0) g_is64 = !bad;
}
__device__ __forceinline__ int edge_idx(const void* __restrict__ ei_raw,
                                        int E, int which, int e) {
    long long v;
    if (g_is64) v = ((const long long*)ei_raw)[(size_t)which * E + e];
    else        v = ((const int*)ei_raw)[(size_t)which * E + e];
    unsigned u = (unsigned)v;
    return (u < NN) ? (int)u : 0;
}

// -------------------- CSR build --------------------------------------------
__global__ void k_zero() {
    int i = blockIdx.x * blockDim.x + threadIdx.x;
    if (i < NN) { g_cnt[i] = 0; g_fill[i] = 0; }
}
__global__ void k_hist(const void* __restrict__ ei, int E) {
    int e = blockIdx.x * blockDim.x + threadIdx.x;
    if (e < E) atomicAdd(&g_cnt[edge_idx(ei, E, 1, e)], 1);
}
__global__ void k_scan1() {
    __shared__ int sh[256];
    int t = threadIdx.x;
    int i = blockIdx.x * 256 + t;
    int v = (i < NN) ? g_cnt[i] : 0;
    sh[t] = v;
    __syncthreads();
#pragma unroll
    for (int o = 1; o < 256; o <<= 1) {
        int u = (t >= o) ? sh[t - o] : 0;
        __syncthreads();
        sh[t] += u;
        __syncthreads();
    }
    if (i < NN) g_ptr[i] = sh[t] - v;          // exclusive within block
    if (t == 255) g_part[blockIdx.x] = sh[255];
}
__global__ void k_scan2() {
    __shared__ int sh[512];
    int t = threadIdx.x;
    int v = (t < NBLK) ? g_part[t] : 0;
    sh[t] = v;
    __syncthreads();
#pragma unroll
    for (int o = 1; o < 512; o <<= 1) {
        int u = (t >= o) ? sh[t - o] : 0;
        __syncthreads();
        sh[t] += u;
        __syncthreads();
    }
    if (t < NBLK) g_poff[t] = sh[t] - v;       // exclusive
}
__global__ void k_scan3(int E) {
    int i = blockIdx.x * blockDim.x + threadIdx.x;
    if (i < NN) g_ptr[i] += g_poff[blockIdx.x];
    if (i == 0) g_ptr[NN] = E;
}
__global__ void k_fill(const void* __restrict__ ei, int E) {
    int e = blockIdx.x * blockDim.x + threadIdx.x;
    if (e >= E) return;
    int src = edge_idx(ei, E, 0, e);
    int dst = edge_idx(ei, E, 1, e);
    int slot = g_ptr[dst] + atomicAdd(&g_fill[dst], 1);
    if (slot < EMAX) g_csr[slot] = src;
}
__global__ void k_dinv() {
    int i = blockIdx.x * blockDim.x + threadIdx.x;
    if (i < NN) g_dinv[i] = rsqrtf(1.0f + (float)g_cnt[i]);
}

// -------------------- W transpose + bf16 split: W[K,N] -> Wt[N,K] hi/lo ----
template <int LAYER>
__global__ void k_wsplit(const float* __restrict__ W) {
    constexpr int K = (LAYER == 1) ? FIN : HH;
    constexpr int N = (LAYER == 1) ? HH  : DOUT;
    __nv_bfloat16* __restrict__ oh = (LAYER == 1) ? g_w1th : g_w2th;
    __nv_bfloat16* __restrict__ ol = (LAYER == 1) ? g_w1tl : g_w2tl;
    int idx = blockIdx.x * blockDim.x + threadIdx.x;
    if (idx >= K * N) return;
    int k = idx / N, n = idx % N;
    unsigned short h, l;
    split_bf16(W[idx], h, l);
    oh[(size_t)n * K + k] = __ushort_as_bfloat16(h);
    ol[(size_t)n * K + k] = __ushort_as_bfloat16(l);
}

// -------------------- bf16 split-3 GEMM via mma.sync (HMMA) ----------------
// C = (A @ W) * dinv[row].  Block 128x128xBK32, 8 warps (4m x 2n), warp 32x64.
template <int LAYER>
__global__ __launch_bounds__(256, 1)
void k_gemm_mma(const float* __restrict__ x) {
    constexpr int K  = (LAYER == 1) ? FIN : HH;
    constexpr int N  = (LAYER == 1) ? HH  : DOUT;
    constexpr int M  = NN;
    constexpr int BK = 32;
    constexpr int NIT = K / BK;
    constexpr int ASTR = 80;
    constexpr int AH = 0, AL = 10240, BHo = 20480, BLo = 30720;

    extern __shared__ char smem[];
    const uint32_t sb = smem_u32(smem);

    const __nv_bfloat16* __restrict__ Wth = (LAYER == 1) ? g_w1th : g_w2th;
    const __nv_bfloat16* __restrict__ Wtl = (LAYER == 1) ? g_w1tl : g_w2tl;
    float* __restrict__ C0 = (LAYER == 1) ? g_hs1 : g_hs2;

    const int tid  = threadIdx.x;
    const int lane = tid & 31;
    const int wid  = tid >> 5;
    const int wm   = (wid & 3) * 32;
    const int wn   = (wid >> 2) * 64;
    const int m0   = blockIdx.y * 128;
    const int n0   = blockIdx.x * 128;

    const int a_rs = (lane & 7) + ((lane >> 3) & 1) * 8;
    const int a_ch = lane >> 4;
    uint32_t a_base[2];
#pragma unroll
    for (int mt = 0; mt < 2; mt++)
        a_base[mt] = sb + AH + (uint32_t)(wm + mt * 16 + a_rs) * ASTR + a_ch * 16;
    const int b_row = (lane & 7) + (lane >> 4) * 8;
    const int b_ch  = (lane >> 3) & 1;
    uint32_t b_base[4];
#pragma unroll
    for (int p = 0; p < 4; p++)
        b_base[p] = sb + BHo + (uint32_t)(wn + p * 16 + b_row) * ASTR + b_ch * 16;

    float acc[2][8][4];
#pragma unroll
    for (int i = 0; i < 2; i++)
#pragma unroll
        for (int j = 0; j < 8; j++)
#pragma unroll
            for (int q = 0; q < 4; q++) acc[i][j][q] = 0.0f;

    float4 fa[4];
    uint4 vah[2], val[2], vbh[2], vbl[2];

    auto ldg = [&](int it) {
        const int k0 = it * BK;
#pragma unroll
        for (int s = 0; s < 2; s++) {
            int lin = s * 256 + tid;
            int row = lin >> 2, c4 = lin & 3;
            int gm = m0 + row;
            if constexpr (LAYER == 1) {
                if (gm < M) {
                    fa[s * 2]     = *(const float4*)&x[(size_t)gm * K + k0 + c4 * 8];
                    fa[s * 2 + 1] = *(const float4*)&x[(size_t)gm * K + k0 + c4 * 8 + 4];
                } else {
                    fa[s * 2] = fa[s * 2 + 1] = make_float4(0.f, 0.f, 0.f, 0.f);
                }
            } else {
                if (gm < M) {
                    vah[s] = *(const uint4*)((const unsigned short*)g_h1h + (size_t)gm * K + k0 + c4 * 8);
                    val[s] = *(const uint4*)((const unsigned short*)g_h1l + (size_t)gm * K + k0 + c4 * 8);
                } else {
                    vah[s] = val[s] = make_uint4(0, 0, 0, 0);
                }
            }
            vbh[s] = *(const uint4*)((const unsigned short*)Wth + (size_t)(n0 + row) * K + k0 + c4 * 8);
            vbl[s] = *(const uint4*)((const unsigned short*)Wtl + (size_t)(n0 + row) * K + k0 + c4 * 8);
        }
    };

    auto sts = [&]() {
#pragma unroll
        for (int s = 0; s < 2; s++) {
            int lin = s * 256 + tid;
            int row = lin >> 2, c4 = lin & 3;
            uint32_t off = (uint32_t)row * ASTR + c4 * 16;
            if constexpr (LAYER == 1) {
                uint4 H, L;
                split8(fa[s * 2], fa[s * 2 + 1], H, L);
                *(uint4*)(smem + AH + off) = H;
                *(uint4*)(smem + AL + off) = L;
            } else {
                *(uint4*)(smem + AH + off) = vah[s];
                *(uint4*)(smem + AL + off) = val[s];
            }
            *(uint4*)(smem + BHo + off) = vbh[s];
            *(uint4*)(smem + BLo + off) = vbl[s];
        }
    };

    auto compute = [&]() {
#pragma unroll
        for (int ks = 0; ks < 2; ks++) {
            uint32_t ah[2][4], al[2][4], bf[8][2];
            ldmx4(ah[0], a_base[0] + ks * 32);
            ldmx4(ah[1], a_base[1] + ks * 32);
            ldmx4(al[0], a_base[0] + (AL - AH) + ks * 32);
            ldmx4(al[1], a_base[1] + (AL - AH) + ks * 32);
#pragma unroll
            for (int p = 0; p < 4; p++) {
                uint32_t r[4];
                ldmx4(r, b_base[p] + ks * 32);
                bf[2 * p][0] = r[0]; bf[2 * p][1] = r[1];
                bf[2 * p + 1][0] = r[2]; bf[2 * p + 1][1] = r[3];
            }
#pragma unroll
            for (int mt = 0; mt < 2; mt++)
#pragma unroll
                for (int nt = 0; nt < 8; nt++) mma_bf16(acc[mt][nt], ah[mt], bf[nt]);
#pragma unroll
            for (int mt = 0; mt < 2; mt++)
#pragma unroll
                for (int nt = 0; nt < 8; nt++) mma_bf16(acc[mt][nt], al[mt], bf[nt]);
#pragma unroll
            for (int p = 0; p < 4; p++) {
                uint32_t r[4];
                ldmx4(r, b_base[p] + (BLo - BHo) + ks * 32);
                bf[2 * p][0] = r[0]; bf[2 * p][1] = r[1];
                bf[2 * p + 1][0] = r[2]; bf[2 * p + 1][1] = r[3];
            }
#pragma unroll
            for (int mt = 0; mt < 2; mt++)
#pragma unroll
                for (int nt = 0; nt < 8; nt++) mma_bf16(acc[mt][nt], ah[mt], bf[nt]);
        }
    };

    ldg(0);
    sts();
    __syncthreads();
    for (int it = 1; it < NIT; it++) {
        ldg(it);
        compute();
        __syncthreads();
        sts();
        __syncthreads();
    }
    compute();
    __syncthreads();

    // epilogue: acc -> smem [128][132] fp32 -> scaled coalesced store
    float* Ds = (float*)smem;
#pragma unroll
    for (int mt = 0; mt < 2; mt++)
#pragma unroll
        for (int nt = 0; nt < 8; nt++) {
            int r0 = wm + mt * 16 + (lane >> 2);
            int col = wn + nt * 8 + (lane & 3) * 2;
            Ds[r0 * 132 + col]           = acc[mt][nt][0];
            Ds[r0 * 132 + col + 1]       = acc[mt][nt][1];
            Ds[(r0 + 8) * 132 + col]     = acc[mt][nt][2];
            Ds[(r0 + 8) * 132 + col + 1] = acc[mt][nt][3];
        }
    __syncthreads();
#pragma unroll
    for (int i = 0; i < 16; i++) {
        int row = i * 8 + wid;
        int gm = m0 + row;
        if (gm < M) {
            float s = g_dinv[gm];
            float4 v = *(float4*)&Ds[row * 132 + lane * 4];
            v.x *= s; v.y *= s; v.z *= s; v.w *= s;
            *(float4*)&C0[(size_t)gm * N + n0 + lane * 4] = v;
        }
    }
}

// -------------------- fused gather-aggregate + bias (+relu/split) ----------
// node i: r = (hs[i] + sum_{j in CSR[i]} hs[src_j]) * dinv[i] + bias
// LAYER 1: relu + bf16 split -> g_h1h/g_h1l;  LAYER 2: -> out.
template <int LAYER>
__global__ void k_gather(const float* __restrict__ bias, float* __restrict__ out_param) {
    constexpr int NC = (LAYER == 1) ? HH : DOUT;
    constexpr int CH = NC / 4;
    const float* __restrict__ hs = (LAYER == 1) ? g_hs1 : g_hs2;

    int gtid = blockIdx.x * blockDim.x + threadIdx.x;
    int node = gtid / CH;
    if (node >= NN) return;
    int c = (gtid % CH) * 4;

    float4 v = *(const float4*)&hs[(size_t)node * NC + c];   // self loop
    int beg = g_ptr[node], end = g_ptr[node + 1];
    int j = beg;
    for (; j + 1 < end; j += 2) {
        int s0 = g_csr[j], s1 = g_csr[j + 1];
        float4 a = *(const float4*)&hs[(size_t)s0 * NC + c];
        float4 b = *(const float4*)&hs[(size_t)s1 * NC + c];
        v.x += a.x + b.x; v.y += a.y + b.y; v.z += a.z + b.z; v.w += a.w + b.w;
    }
    if (j < end) {
        int s0 = g_csr[j];
        float4 a = *(const float4*)&hs[(size_t)s0 * NC + c];
        v.x += a.x; v.y += a.y; v.z += a.z; v.w += a.w;
    }

    float s = g_dinv[node];
    float4 b = *(const float4*)&bias[c];
    float4 r = make_float4(fmaf(v.x, s, b.x), fmaf(v.y, s, b.y),
                           fmaf(v.z, s, b.z), fmaf(v.w, s, b.w));
    if (LAYER == 1) {
        r.x = fmaxf(r.x, 0.f); r.y = fmaxf(r.y, 0.f);
        r.z = fmaxf(r.z, 0.f); r.w = fmaxf(r.w, 0.f);
        unsigned short h0, h1, h2, h3, l0, l1, l2, l3;
        split_bf16(r.x, h0, l0); split_bf16(r.y, h1, l1);
        split_bf16(r.z, h2, l2); split_bf16(r.w, h3, l3);
        uint2 uh = make_uint2((uint32_t)h0 | ((uint32_t)h1 << 16),
                              (uint32_t)h2 | ((uint32_t)h3 << 16));
        uint2 ul = make_uint2((uint32_t)l0 | ((uint32_t)l1 << 16),
                              (uint32_t)l2 | ((uint32_t)l3 << 16));
        *(uint2*)((unsigned short*)g_h1h + (size_t)node * NC + c) = uh;
        *(uint2*)((unsigned short*)g_h1l + (size_t)node * NC + c) = ul;
    } else {
        *(float4*)&out_param[(size_t)node * NC + c] = r;
    }
}

// ---------------------------------------------------------------------------
extern "C" void kernel_launch(void* const* d_in, const int* in_sizes, int n_in,
                              void* d_out, int out_size) {
    const float* x  = (const float*)d_in[0];
    const void*  ei = d_in[1];
    const float* W1 = (const float*)d_in[2];
    const float* b1 = (const float*)d_in[3];
    const float* W2 = (const float*)d_in[4];
    const float* b2 = (const float*)d_in[5];
    float*       out = (float*)d_out;

    const int E = in_sizes[1] / 2;
    const int MB = (NN + 127) / 128;
    const int SMEM = 128 * 132 * 4;

    cudaFuncSetAttribute(k_gemm_mma<1>, cudaFuncAttributeMaxDynamicSharedMemorySize, SMEM);
    cudaFuncSetAttribute(k_gemm_mma<2>, cudaFuncAttributeMaxDynamicSharedMemorySize, SMEM);

    // 0. edge dtype + CSR build + normalization + W preprocessing
    k_detect<<<1, 256>>>(ei, E);
    k_zero <<<NBLK, 256>>>();
    k_hist <<<(E + 255) / 256, 256>>>(ei, E);
    k_scan1<<<NBLK, 256>>>();
    k_scan2<<<1, 512>>>();
    k_scan3<<<NBLK, 256>>>(E);
    k_fill <<<(E + 255) / 256, 256>>>(ei, E);
    k_dinv <<<NBLK, 256>>>();
    k_wsplit<1><<<(FIN * HH + 255) / 256, 256>>>(W1);
    k_wsplit<2><<<(HH * DOUT + 255) / 256, 256>>>(W2);

    // layer 1
    k_gemm_mma<1><<<dim3(HH / 128, MB), 256, SMEM>>>(x);
    k_gather<1><<<(NN * (HH / 4) + 255) / 256, 256>>>(b1, nullptr);
    // layer 2
    k_gemm_mma<2><<<dim3(DOUT / 128, MB), 256, SMEM>>>(nullptr);
    k_gather<2><<<(NN * (DOUT / 4) + 255) / 256, 256>>>(b2, out);
}

// round 10
// speedup vs baseline: 3.4040x; 1.1495x over previous
#include <cuda_runtime.h>
#include <cuda_bf16.h>
#include <cstdint>

// Problem shapes (fixed for GCNNet_61323543052323)
#define NN   100000
#define FIN  512
#define HH   256
#define DOUT 128
#define EMAX 800000
#define NBLK ((NN + 255) / 256)

// -------------------- scratch (device globals) ------------------------------
__device__ __align__(128) float g_dinv[NN];
__device__ __align__(128) float g_hs1 [(size_t)NN * HH];
__device__ __align__(128) float g_hs2 [(size_t)NN * DOUT];
__device__ __align__(128) __nv_bfloat16 g_h1h[(size_t)NN * HH];
__device__ __align__(128) __nv_bfloat16 g_h1l[(size_t)NN * HH];
__device__ __align__(128) __nv_bfloat16 g_w1th[(size_t)HH * FIN]; // W1^T hi [N][K]
__device__ __align__(128) __nv_bfloat16 g_w1tl[(size_t)HH * FIN];
__device__ __align__(128) __nv_bfloat16 g_w2th[(size_t)DOUT * HH];
__device__ __align__(128) __nv_bfloat16 g_w2tl[(size_t)DOUT * HH];
// CSR by destination
__device__ __align__(128) int g_cnt [NN];
__device__ __align__(128) int g_fill[NN];
__device__ __align__(128) int g_ptr [NN + 1];
__device__ __align__(128) int g_part[NBLK];
__device__ __align__(128) int g_poff[NBLK];
__device__ __align__(128) int g_csr [EMAX];
__device__ int g_is64;

// -------------------- helpers ----------------------------------------------
__device__ __forceinline__ uint32_t smem_u32(const void* p) {
    uint32_t a;
    asm("{ .reg .u64 t; cvta.to.shared.u64 t, %1; cvt.u32.u64 %0, t; }" : "=r"(a) : "l"(p));
    return a;
}
__device__ __forceinline__ void ldmx4(uint32_t* r, uint32_t addr) {
    asm volatile("ldmatrix.sync.aligned.m8n8.x4.shared.b16 {%0,%1,%2,%3}, [%4];"
                 : "=r"(r[0]), "=r"(r[1]), "=r"(r[2]), "=r"(r[3]) : "r"(addr));
}
__device__ __forceinline__ void mma_bf16(float* d, const uint32_t* a, const uint32_t* b) {
    asm volatile(
        "mma.sync.aligned.m16n8k16.row.col.f32.bf16.bf16.f32 "
        "{%0,%1,%2,%3}, {%4,%5,%6,%7}, {%8,%9}, {%0,%1,%2,%3};"
        : "+f"(d[0]), "+f"(d[1]), "+f"(d[2]), "+f"(d[3])
        : "r"(a[0]), "r"(a[1]), "r"(a[2]), "r"(a[3]), "r"(b[0]), "r"(b[1]));
}
__device__ __forceinline__ void split_bf16(float v, unsigned short& h, unsigned short& l) {
    __nv_bfloat16 bh = __float2bfloat16_rn(v);
    float r = v - __bfloat162float(bh);
    h = __bfloat16_as_ushort(bh);
    l = __bfloat16_as_ushort(__float2bfloat16_rn(r));
}
__device__ __forceinline__ void split8(const float4& f0, const float4& f1, uint4& H, uint4& L) {
    unsigned short h[8], l[8];
    split_bf16(f0.x, h[0], l[0]); split_bf16(f0.y, h[1], l[1]);
    split_bf16(f0.z, h[2], l[2]); split_bf16(f0.w, h[3], l[3]);
    split_bf16(f1.x, h[4], l[4]); split_bf16(f1.y, h[5], l[5]);
    split_bf16(f1.z, h[6], l[6]); split_bf16(f1.w, h[7], l[7]);
    H = make_uint4((uint32_t)h[0] | ((uint32_t)h[1] << 16), (uint32_t)h[2] | ((uint32_t)h[3] << 16),
                   (uint32_t)h[4] | ((uint32_t)h[5] << 16), (uint32_t)h[6] | ((uint32_t)h[7] << 16));
    L = make_uint4((uint32_t)l[0] | ((uint32_t)l[1] << 16), (uint32_t)l[2] | ((uint32_t)l[3] << 16),
                   (uint32_t)l[4] | ((uint32_t)l[5] << 16), (uint32_t)l[6] | ((uint32_t)l[7] << 16));
}

// -------------------- edge index access ------------------------------------
__device__ __forceinline__ int edge_idx(const void* __restrict__ ei_raw,
                                        int E, int which, int e) {
    long long v;
    if (g_is64) v = ((const long long*)ei_raw)[(size_t)which * E + e];
    else        v = ((const int*)ei_raw)[(size_t)which * E + e];
    unsigned u = (unsigned)v;
    return (u < NN) ? (int)u : 0;
}

// -------------------- CSR build (detect fused into zero) -------------------
__global__ void k_zero(const void* __restrict__ ei_raw, int E) {
    int i = blockIdx.x * blockDim.x + threadIdx.x;
    if (i < NN) { g_cnt[i] = 0; g_fill[i] = 0; }
    if (blockIdx.x == 0) {                      // fused dtype detection
        const long long* p = (const long long*)ei_raw;
        int bad = 0;
        int n = (E < 1024) ? E : 1024;
        for (int j = threadIdx.x; j < n; j += 256) {
            long long v = p[j];
            if (v < 0 || v >= NN) bad = 1;
        }
        bad = __syncthreads_or(bad);
        if (threadIdx.x == 0) g_is64 = !bad;
    }
}
__global__ void k_hist(const void* __restrict__ ei, int E) {
    int e = blockIdx.x * blockDim.x + threadIdx.x;
    if (e < E) atomicAdd(&g_cnt[edge_idx(ei, E, 1, e)], 1);
}
__global__ void k_scan1() {
    __shared__ int sh[256];
    int t = threadIdx.x;
    int i = blockIdx.x * 256 + t;
    int v = (i < NN) ? g_cnt[i] : 0;
    sh[t] = v;
    __syncthreads();
#pragma unroll
    for (int o = 1; o < 256; o <<= 1) {
        int u = (t >= o) ? sh[t - o] : 0;
        __syncthreads();
        sh[t] += u;
        __syncthreads();
    }
    if (i < NN) g_ptr[i] = sh[t] - v;
    if (t == 255) g_part[blockIdx.x] = sh[255];
}
__global__ void k_scan2() {
    __shared__ int sh[512];
    int t = threadIdx.x;
    int v = (t < NBLK) ? g_part[t] : 0;
    sh[t] = v;
    __syncthreads();
#pragma unroll
    for (int o = 1; o < 512; o <<= 1) {
        int u = (t >= o) ? sh[t - o] : 0;
        __syncthreads();
        sh[t] += u;
        __syncthreads();
    }
    if (t < NBLK) g_poff[t] = sh[t] - v;
}
__global__ void k_scan3(int E) {          // + fused dinv
    int i = blockIdx.x * blockDim.x + threadIdx.x;
    if (i < NN) {
        g_ptr[i] += g_poff[blockIdx.x];
        g_dinv[i] = rsqrtf(1.0f + (float)g_cnt[i]);
    }
    if (i == 0) g_ptr[NN] = E;
}
__global__ void k_fill(const void* __restrict__ ei, int E) {
    int e = blockIdx.x * blockDim.x + threadIdx.x;
    if (e >= E) return;
    int src = edge_idx(ei, E, 0, e);
    int dst = edge_idx(ei, E, 1, e);
    int slot = g_ptr[dst] + atomicAdd(&g_fill[dst], 1);
    if (slot < EMAX) g_csr[slot] = src;
}

// -------------------- W transpose + bf16 split: W[K,N] -> Wt[N,K] hi/lo ----
template <int LAYER>
__global__ void k_wsplit(const float* __restrict__ W) {
    constexpr int K = (LAYER == 1) ? FIN : HH;
    constexpr int N = (LAYER == 1) ? HH  : DOUT;
    __nv_bfloat16* __restrict__ oh = (LAYER == 1) ? g_w1th : g_w2th;
    __nv_bfloat16* __restrict__ ol = (LAYER == 1) ? g_w1tl : g_w2tl;
    int idx = blockIdx.x * blockDim.x + threadIdx.x;
    if (idx >= K * N) return;
    int k = idx / N, n = idx % N;
    unsigned short h, l;
    split_bf16(W[idx], h, l);
    oh[(size_t)n * K + k] = __ushort_as_bfloat16(h);
    ol[(size_t)n * K + k] = __ushort_as_bfloat16(l);
}

// -------------------- bf16 split-3 GEMM via mma.sync (HMMA) ----------------
// C = (A @ W) * dinv[row].  Block 128x128xBK32, 8 warps (4m x 2n), warp 32x64.
// Double-buffered smem stages; direct-register epilogue.
template <int LAYER>
__global__ __launch_bounds__(256, 1)
void k_gemm_mma(const float* __restrict__ x) {
    constexpr int K  = (LAYER == 1) ? FIN : HH;
    constexpr int N  = (LAYER == 1) ? HH  : DOUT;
    constexpr int M  = NN;
    constexpr int BK = 32;
    constexpr int NIT = K / BK;
    constexpr int ASTR = 80;                 // bytes per row (32 bf16 + pad)
    constexpr int AH = 0, AL = 10240, BHo = 20480, BLo = 30720;
    constexpr int STG = 40960;               // stage size

    extern __shared__ char smem[];
    const uint32_t sb = smem_u32(smem);

    const __nv_bfloat16* __restrict__ Wth = (LAYER == 1) ? g_w1th : g_w2th;
    const __nv_bfloat16* __restrict__ Wtl = (LAYER == 1) ? g_w1tl : g_w2tl;
    float* __restrict__ C0 = (LAYER == 1) ? g_hs1 : g_hs2;

    const int tid  = threadIdx.x;
    const int lane = tid & 31;
    const int wid  = tid >> 5;
    const int wm   = (wid & 3) * 32;
    const int wn   = (wid >> 2) * 64;
    const int m0   = blockIdx.y * 128;
    const int n0   = blockIdx.x * 128;

    const int a_rs = (lane & 7) + ((lane >> 3) & 1) * 8;
    const int a_ch = lane >> 4;
    uint32_t a_base[2];
#pragma unroll
    for (int mt = 0; mt < 2; mt++)
        a_base[mt] = sb + AH + (uint32_t)(wm + mt * 16 + a_rs) * ASTR + a_ch * 16;
    const int b_row = (lane & 7) + (lane >> 4) * 8;
    const int b_ch  = (lane >> 3) & 1;
    uint32_t b_base[4];
#pragma unroll
    for (int p = 0; p < 4; p++)
        b_base[p] = sb + BHo + (uint32_t)(wn + p * 16 + b_row) * ASTR + b_ch * 16;

    float acc[2][8][4];
#pragma unroll
    for (int i = 0; i < 2; i++)
#pragma unroll
        for (int j = 0; j < 8; j++)
#pragma unroll
            for (int q = 0; q < 4; q++) acc[i][j][q] = 0.0f;

    float4 fa[4];
    uint4 vah[2], val[2], vbh[2], vbl[2];

    auto ldg = [&](int it) {
        const int k0 = it * BK;
#pragma unroll
        for (int s = 0; s < 2; s++) {
            int lin = s * 256 + tid;
            int row = lin >> 2, c4 = lin & 3;
            int gm = m0 + row;
            if constexpr (LAYER == 1) {
                if (gm < M) {
                    fa[s * 2]     = *(const float4*)&x[(size_t)gm * K + k0 + c4 * 8];
                    fa[s * 2 + 1] = *(const float4*)&x[(size_t)gm * K + k0 + c4 * 8 + 4];
                } else {
                    fa[s * 2] = fa[s * 2 + 1] = make_float4(0.f, 0.f, 0.f, 0.f);
                }
            } else {
                if (gm < M) {
                    vah[s] = *(const uint4*)((const unsigned short*)g_h1h + (size_t)gm * K + k0 + c4 * 8);
                    val[s] = *(const uint4*)((const unsigned short*)g_h1l + (size_t)gm * K + k0 + c4 * 8);
                } else {
                    vah[s] = val[s] = make_uint4(0, 0, 0, 0);
                }
            }
            vbh[s] = *(const uint4*)((const unsigned short*)Wth + (size_t)(n0 + row) * K + k0 + c4 * 8);
            vbl[s] = *(const uint4*)((const unsigned short*)Wtl + (size_t)(n0 + row) * K + k0 + c4 * 8);
        }
    };

    auto sts = [&](int st) {
        char* base = smem + st * STG;
#pragma unroll
        for (int s = 0; s < 2; s++) {
            int lin = s * 256 + tid;
            int row = lin >> 2, c4 = lin & 3;
            uint32_t off = (uint32_t)row * ASTR + c4 * 16;
            if constexpr (LAYER == 1) {
                uint4 H, L;
                split8(fa[s * 2], fa[s * 2 + 1], H, L);
                *(uint4*)(base + AH + off) = H;
                *(uint4*)(base + AL + off) = L;
            } else {
                *(uint4*)(base + AH + off) = vah[s];
                *(uint4*)(base + AL + off) = val[s];
            }
            *(uint4*)(base + BHo + off) = vbh[s];
            *(uint4*)(base + BLo + off) = vbl[s];
        }
    };

    auto compute = [&](int st) {
        const uint32_t so = st * STG;
#pragma unroll
        for (int ks = 0; ks < 2; ks++) {
            uint32_t ah[2][4], al[2][4], bf[8][2];
            ldmx4(ah[0], a_base[0] + so + ks * 32);
            ldmx4(ah[1], a_base[1] + so + ks * 32);
            ldmx4(al[0], a_base[0] + so + (AL - AH) + ks * 32);
            ldmx4(al[1], a_base[1] + so + (AL - AH) + ks * 32);
#pragma unroll
            for (int p = 0; p < 4; p++) {
                uint32_t r[4];
                ldmx4(r, b_base[p] + so + ks * 32);
                bf[2 * p][0] = r[0]; bf[2 * p][1] = r[1];
                bf[2 * p + 1][0] = r[2]; bf[2 * p + 1][1] = r[3];
            }
#pragma unroll
            for (int mt = 0; mt < 2; mt++)
#pragma unroll
                for (int nt = 0; nt < 8; nt++) mma_bf16(acc[mt][nt], ah[mt], bf[nt]);
#pragma unroll
            for (int mt = 0; mt < 2; mt++)
#pragma unroll
                for (int nt = 0; nt < 8; nt++) mma_bf16(acc[mt][nt], al[mt], bf[nt]);
#pragma unroll
            for (int p = 0; p < 4; p++) {
                uint32_t r[4];
                ldmx4(r, b_base[p] + so + (BLo - BHo) + ks * 32);
                bf[2 * p][0] = r[0]; bf[2 * p][1] = r[1];
                bf[2 * p + 1][0] = r[2]; bf[2 * p + 1][1] = r[3];
            }
#pragma unroll
            for (int mt = 0; mt < 2; mt++)
#pragma unroll
                for (int nt = 0; nt < 8; nt++) mma_bf16(acc[mt][nt], ah[mt], bf[nt]);
        }
    };

    // double-buffered mainloop: 1 sync per iteration
    ldg(0);
    sts(0);
    __syncthreads();
    int cur = 0;
    for (int it = 1; it < NIT; it++) {
        ldg(it);               // prefetch to regs
        compute(cur);          // retire LDGs under compute
        sts(cur ^ 1);          // fill other stage
        __syncthreads();
        cur ^= 1;
    }
    compute(cur);

    // direct-register epilogue: quad-contiguous 32B float2 stores
#pragma unroll
    for (int mt = 0; mt < 2; mt++) {
        int r0 = wm + mt * 16 + (lane >> 2);
        int gm0 = m0 + r0;
        int gm1 = gm0 + 8;
        float s0 = (gm0 < M) ? g_dinv[gm0] : 0.0f;
        float s1 = (gm1 < M) ? g_dinv[gm1] : 0.0f;
#pragma unroll
        for (int nt = 0; nt < 8; nt++) {
            int col = n0 + wn + nt * 8 + (lane & 3) * 2;
            if (gm0 < M)
                *(float2*)&C0[(size_t)gm0 * N + col] =
                    make_float2(acc[mt][nt][0] * s0, acc[mt][nt][1] * s0);
            if (gm1 < M)
                *(float2*)&C0[(size_t)gm1 * N + col] =
                    make_float2(acc[mt][nt][2] * s1, acc[mt][nt][3] * s1);
        }
    }
}

// -------------------- fused gather-aggregate + bias (+relu/split) ----------
template <int LAYER>
__global__ void k_gather(const float* __restrict__ bias, float* __restrict__ out_param) {
    constexpr int NC = (LAYER == 1) ? HH : DOUT;
    constexpr int CH = NC / 4;
    const float* __restrict__ hs = (LAYER == 1) ? g_hs1 : g_hs2;

    int gtid = blockIdx.x * blockDim.x + threadIdx.x;
    int node = gtid / CH;
    if (node >= NN) return;
    int c = (gtid % CH) * 4;

    float4 v = *(const float4*)&hs[(size_t)node * NC + c];   // self loop
    int beg = g_ptr[node], end = g_ptr[node + 1];
    int j = beg;
    for (; j + 1 < end; j += 2) {
        int s0 = g_csr[j], s1 = g_csr[j + 1];
        float4 a = *(const float4*)&hs[(size_t)s0 * NC + c];
        float4 b = *(const float4*)&hs[(size_t)s1 * NC + c];
        v.x += a.x + b.x; v.y += a.y + b.y; v.z += a.z + b.z; v.w += a.w + b.w;
    }
    if (j < end) {
        int s0 = g_csr[j];
        float4 a = *(const float4*)&hs[(size_t)s0 * NC + c];
        v.x += a.x; v.y += a.y; v.z += a.z; v.w += a.w;
    }

    float s = g_dinv[node];
    float4 b = *(const float4*)&bias[c];
    float4 r = make_float4(fmaf(v.x, s, b.x), fmaf(v.y, s, b.y),
                           fmaf(v.z, s, b.z), fmaf(v.w, s, b.w));
    if (LAYER == 1) {
        r.x = fmaxf(r.x, 0.f); r.y = fmaxf(r.y, 0.f);
        r.z = fmaxf(r.z, 0.f); r.w = fmaxf(r.w, 0.f);
        unsigned short h0, h1, h2, h3, l0, l1, l2, l3;
        split_bf16(r.x, h0, l0); split_bf16(r.y, h1, l1);
        split_bf16(r.z, h2, l2); split_bf16(r.w, h3, l3);
        uint2 uh = make_uint2((uint32_t)h0 | ((uint32_t)h1 << 16),
                              (uint32_t)h2 | ((uint32_t)h3 << 16));
        uint2 ul = make_uint2((uint32_t)l0 | ((uint32_t)l1 << 16),
                              (uint32_t)l2 | ((uint32_t)l3 << 16));
        *(uint2*)((unsigned short*)g_h1h + (size_t)node * NC + c) = uh;
        *(uint2*)((unsigned short*)g_h1l + (size_t)node * NC + c) = ul;
    } else {
        *(float4*)&out_param[(size_t)node * NC + c] = r;
    }
}

// ---------------------------------------------------------------------------
extern "C" void kernel_launch(void* const* d_in, const int* in_sizes, int n_in,
                              void* d_out, int out_size) {
    const float* x  = (const float*)d_in[0];
    const void*  ei = d_in[1];
    const float* W1 = (const float*)d_in[2];
    const float* b1 = (const float*)d_in[3];
    const float* W2 = (const float*)d_in[4];
    const float* b2 = (const float*)d_in[5];
    float*       out = (float*)d_out;

    const int E = in_sizes[1] / 2;
    const int MB = (NN + 127) / 128;
    const int SMEM = 2 * 40960;

    cudaFuncSetAttribute(k_gemm_mma<1>, cudaFuncAttributeMaxDynamicSharedMemorySize, SMEM);
    cudaFuncSetAttribute(k_gemm_mma<2>, cudaFuncAttributeMaxDynamicSharedMemorySize, SMEM);

    // 0. CSR build + normalization + W preprocessing
    k_zero <<<NBLK, 256>>>(ei, E);
    k_hist <<<(E + 255) / 256, 256>>>(ei, E);
    k_scan1<<<NBLK, 256>>>();
    k_scan2<<<1, 512>>>();
    k_scan3<<<NBLK, 256>>>(E);
    k_fill <<<(E + 255) / 256, 256>>>(ei, E);
    k_wsplit<1><<<(FIN * HH + 255) / 256, 256>>>(W1);
    k_wsplit<2><<<(HH * DOUT + 255) / 256, 256>>>(W2);

    // layer 1
    k_gemm_mma<1><<<dim3(HH / 128, MB), 256, SMEM>>>(x);
    k_gather<1><<<(NN * (HH / 4) + 255) / 256, 256>>>(b1, nullptr);
    // layer 2
    k_gemm_mma<2><<<dim3(DOUT / 128, MB), 256, SMEM>>>(nullptr);
    k_gather<2><<<(NN * (DOUT / 4) + 255) / 256, 256>>>(b2, out);
}

// round 11
// speedup vs baseline: 3.7386x; 1.0983x over previous
#include <cuda_runtime.h>
#include <cuda_bf16.h>
#include <cstdint>

// Problem shapes (fixed for GCNNet_61323543052323)
#define NN   100000
#define FIN  512
#define HH   256
#define DOUT 128
#define EMAX 800000
#define NBLK ((NN + 255) / 256)

// -------------------- scratch (device globals) ------------------------------
__device__ __align__(128) float g_dinv[NN];
__device__ __align__(128) float g_hs1 [(size_t)NN * HH];
__device__ __align__(128) float g_hs2 [(size_t)NN * DOUT];
__device__ __align__(128) __nv_bfloat16 g_h1h[(size_t)NN * HH];
__device__ __align__(128) __nv_bfloat16 g_h1l[(size_t)NN * HH];
__device__ __align__(128) __nv_bfloat16 g_w1th[(size_t)HH * FIN]; // W1^T hi [N][K]
__device__ __align__(128) __nv_bfloat16 g_w1tl[(size_t)HH * FIN];
__device__ __align__(128) __nv_bfloat16 g_w2th[(size_t)DOUT * HH];
__device__ __align__(128) __nv_bfloat16 g_w2tl[(size_t)DOUT * HH];
// CSR by destination (segment bases via atomic counter; order irrelevant)
__device__ __align__(128) int g_cnt [NN];
__device__ __align__(128) int g_fill[NN];
__device__ __align__(128) int g_ptr [NN];
__device__ __align__(128) int g_csr [EMAX];
__device__ int g_total;
__device__ int g_is64;

// -------------------- helpers ----------------------------------------------
__device__ __forceinline__ uint32_t smem_u32(const void* p) {
    uint32_t a;
    asm("{ .reg .u64 t; cvta.to.shared.u64 t, %1; cvt.u32.u64 %0, t; }" : "=r"(a) : "l"(p));
    return a;
}
__device__ __forceinline__ void ldmx4(uint32_t* r, uint32_t addr) {
    asm volatile("ldmatrix.sync.aligned.m8n8.x4.shared.b16 {%0,%1,%2,%3}, [%4];"
                 : "=r"(r[0]), "=r"(r[1]), "=r"(r[2]), "=r"(r[3]) : "r"(addr));
}
__device__ __forceinline__ void mma_bf16(float* d, const uint32_t* a, const uint32_t* b) {
    asm volatile(
        "mma.sync.aligned.m16n8k16.row.col.f32.bf16.bf16.f32 "
        "{%0,%1,%2,%3}, {%4,%5,%6,%7}, {%8,%9}, {%0,%1,%2,%3};"
        : "+f"(d[0]), "+f"(d[1]), "+f"(d[2]), "+f"(d[3])
        : "r"(a[0]), "r"(a[1]), "r"(a[2]), "r"(a[3]), "r"(b[0]), "r"(b[1]));
}
__device__ __forceinline__ void cp16(uint32_t dst, const void* src) {
    asm volatile("cp.async.cg.shared.global [%0], [%1], 16;" :: "r"(dst), "l"(src));
}
__device__ __forceinline__ void cp16p(uint32_t dst, const void* src, int bytes) {
    asm volatile("cp.async.cg.shared.global [%0], [%1], 16, %2;"
                 :: "r"(dst), "l"(src), "r"(bytes));   // bytes==0 -> zero fill
}
__device__ __forceinline__ void cp_commit() { asm volatile("cp.async.commit_group;"); }
__device__ __forceinline__ void cp_wait0()  { asm volatile("cp.async.wait_group 0;" ::: "memory"); }

__device__ __forceinline__ void split_bf16(float v, unsigned short& h, unsigned short& l) {
    __nv_bfloat16 bh = __float2bfloat16_rn(v);
    float r = v - __bfloat162float(bh);
    h = __bfloat16_as_ushort(bh);
    l = __bfloat16_as_ushort(__float2bfloat16_rn(r));
}
__device__ __forceinline__ void split8(const float4& f0, const float4& f1, uint4& H, uint4& L) {
    unsigned short h[8], l[8];
    split_bf16(f0.x, h[0], l[0]); split_bf16(f0.y, h[1], l[1]);
    split_bf16(f0.z, h[2], l[2]); split_bf16(f0.w, h[3], l[3]);
    split_bf16(f1.x, h[4], l[4]); split_bf16(f1.y, h[5], l[5]);
    split_bf16(f1.z, h[6], l[6]); split_bf16(f1.w, h[7], l[7]);
    H = make_uint4((uint32_t)h[0] | ((uint32_t)h[1] << 16), (uint32_t)h[2] | ((uint32_t)h[3] << 16),
                   (uint32_t)h[4] | ((uint32_t)h[5] << 16), (uint32_t)h[6] | ((uint32_t)h[7] << 16));
    L = make_uint4((uint32_t)l[0] | ((uint32_t)l[1] << 16), (uint32_t)l[2] | ((uint32_t)l[3] << 16),
                   (uint32_t)l[4] | ((uint32_t)l[5] << 16), (uint32_t)l[6] | ((uint32_t)l[7] << 16));
}

// -------------------- edge index access ------------------------------------
__device__ __forceinline__ int edge_idx(const void* __restrict__ ei_raw,
                                        int E, int which, int e) {
    long long v;
    if (g_is64) v = ((const long long*)ei_raw)[(size_t)which * E + e];
    else        v = ((const int*)ei_raw)[(size_t)which * E + e];
    unsigned u = (unsigned)v;
    return (u < NN) ? (int)u : 0;
}

// -------------------- fused preproc 0: zero + detect + both wsplits --------
__global__ void k_pre0(const void* __restrict__ ei_raw, int E,
                       const float* __restrict__ W1, const float* __restrict__ W2) {
    int i = blockIdx.x * blockDim.x + threadIdx.x;
    if (i < NN) { g_cnt[i] = 0; g_fill[i] = 0; }
    if (i == 0) g_total = 0;
    if (i < FIN * HH) {
        int k = i / HH, n = i % HH;
        unsigned short h, l;
        split_bf16(W1[i], h, l);
        g_w1th[(size_t)n * FIN + k] = __ushort_as_bfloat16(h);
        g_w1tl[(size_t)n * FIN + k] = __ushort_as_bfloat16(l);
    }
    if (i < HH * DOUT) {
        int k = i / DOUT, n = i % DOUT;
        unsigned short h, l;
        split_bf16(W2[i], h, l);
        g_w2th[(size_t)n * HH + k] = __ushort_as_bfloat16(h);
        g_w2tl[(size_t)n * HH + k] = __ushort_as_bfloat16(l);
    }
    if (blockIdx.x == 0) {                     // dtype detect
        const long long* p = (const long long*)ei_raw;
        int bad = 0;
        int n = (E < 1024) ? E : 1024;
        for (int j = threadIdx.x; j < n; j += 256) {
            long long v = p[j];
            if (v < 0 || v >= NN) bad = 1;
        }
        bad = __syncthreads_or(bad);
        if (threadIdx.x == 0) g_is64 = !bad;
    }
}
__global__ void k_hist(const void* __restrict__ ei, int E) {
    int e = blockIdx.x * blockDim.x + threadIdx.x;
    if (e < E) atomicAdd(&g_cnt[edge_idx(ei, E, 1, e)], 1);
}
// segment base via atomic counter (order-free CSR) + dinv
__global__ void k_ptrdinv() {
    int i = blockIdx.x * blockDim.x + threadIdx.x;
    if (i < NN) {
        int c = g_cnt[i];
        g_ptr[i]  = atomicAdd(&g_total, c);
        g_dinv[i] = rsqrtf(1.0f + (float)c);
    }
}
__global__ void k_fill(const void* __restrict__ ei, int E) {
    int e = blockIdx.x * blockDim.x + threadIdx.x;
    if (e >= E) return;
    int src = edge_idx(ei, E, 0, e);
    int dst = edge_idx(ei, E, 1, e);
    int slot = g_ptr[dst] + atomicAdd(&g_fill[dst], 1);
    if (slot < EMAX) g_csr[slot] = src;
}

// -------------------- bf16 split-3 GEMM via mma.sync (HMMA) ----------------
// C = (A @ W) * dinv[row].  Block 128x128xBK32, 8 warps (4m x 2n), warp 32x64.
// Double-buffered; B (and layer-2 A) staged via cp.async; 2 CTAs/SM.
template <int LAYER>
__global__ __launch_bounds__(256, 2)
void k_gemm_mma(const float* __restrict__ x) {
    constexpr int K  = (LAYER == 1) ? FIN : HH;
    constexpr int N  = (LAYER == 1) ? HH  : DOUT;
    constexpr int M  = NN;
    constexpr int BK = 32;
    constexpr int NIT = K / BK;
    constexpr int ASTR = 80;
    constexpr int AH = 0, AL = 10240, BHo = 20480, BLo = 30720;
    constexpr int STG = 40960;

    extern __shared__ char smem[];
    const uint32_t sb = smem_u32(smem);

    const __nv_bfloat16* __restrict__ Wth = (LAYER == 1) ? g_w1th : g_w2th;
    const __nv_bfloat16* __restrict__ Wtl = (LAYER == 1) ? g_w1tl : g_w2tl;
    float* __restrict__ C0 = (LAYER == 1) ? g_hs1 : g_hs2;

    const int tid  = threadIdx.x;
    const int lane = tid & 31;
    const int wid  = tid >> 5;
    const int wm   = (wid & 3) * 32;
    const int wn   = (wid >> 2) * 64;
    const int m0   = blockIdx.y * 128;
    const int n0   = blockIdx.x * 128;

    const int a_rs = (lane & 7) + ((lane >> 3) & 1) * 8;
    const int a_ch = lane >> 4;
    uint32_t a_base[2];
#pragma unroll
    for (int mt = 0; mt < 2; mt++)
        a_base[mt] = sb + AH + (uint32_t)(wm + mt * 16 + a_rs) * ASTR + a_ch * 16;
    const int b_row = (lane & 7) + (lane >> 4) * 8;
    const int b_ch  = (lane >> 3) & 1;
    uint32_t b_base[4];
#pragma unroll
    for (int p = 0; p < 4; p++)
        b_base[p] = sb + BHo + (uint32_t)(wn + p * 16 + b_row) * ASTR + b_ch * 16;

    float acc[2][8][4];
#pragma unroll
    for (int i = 0; i < 2; i++)
#pragma unroll
        for (int j = 0; j < 8; j++)
#pragma unroll
            for (int q = 0; q < 4; q++) acc[i][j][q] = 0.0f;

    float4 fa[4];                         // layer-1 A register staging only

    // async staging: B hi/lo (both layers) + A hi/lo (layer 2)
    auto cpa = [&](int it, int st) {
        const int k0 = it * BK;
        const uint32_t base = sb + st * STG;
#pragma unroll
        for (int s = 0; s < 2; s++) {
            int lin = s * 256 + tid;
            int row = lin >> 2, c4 = lin & 3;
            uint32_t off = (uint32_t)row * ASTR + c4 * 16;
            if constexpr (LAYER == 2) {
                int gm = m0 + row;
                int ok = (gm < M) ? 16 : 0;
                cp16p(base + AH + off,
                      (const unsigned short*)g_h1h + (size_t)gm * K + k0 + c4 * 8, ok);
                cp16p(base + AL + off,
                      (const unsigned short*)g_h1l + (size_t)gm * K + k0 + c4 * 8, ok);
            }
            cp16(base + BHo + off,
                 (const unsigned short*)Wth + (size_t)(n0 + row) * K + k0 + c4 * 8);
            cp16(base + BLo + off,
                 (const unsigned short*)Wtl + (size_t)(n0 + row) * K + k0 + c4 * 8);
        }
        cp_commit();
    };

    auto ldgA = [&](int it) {             // layer-1 only: fp32 A into regs
        if constexpr (LAYER == 1) {
            const int k0 = it * BK;
#pragma unroll
            for (int s = 0; s < 2; s++) {
                int lin = s * 256 + tid;
                int row = lin >> 2, c4 = lin & 3;
                int gm = m0 + row;
                if (gm < M) {
                    fa[s * 2]     = *(const float4*)&x[(size_t)gm * K + k0 + c4 * 8];
                    fa[s * 2 + 1] = *(const float4*)&x[(size_t)gm * K + k0 + c4 * 8 + 4];
                } else {
                    fa[s * 2] = fa[s * 2 + 1] = make_float4(0.f, 0.f, 0.f, 0.f);
                }
            }
        }
    };

    auto stsA = [&](int st) {             // layer-1 only: split + store A
        if constexpr (LAYER == 1) {
            char* base = smem + st * STG;
#pragma unroll
            for (int s = 0; s < 2; s++) {
                int lin = s * 256 + tid;
                int row = lin >> 2, c4 = lin & 3;
                uint32_t off = (uint32_t)row * ASTR + c4 * 16;
                uint4 H, L;
                split8(fa[s * 2], fa[s * 2 + 1], H, L);
                *(uint4*)(base + AH + off) = H;
                *(uint4*)(base + AL + off) = L;
            }
        }
    };

    auto compute = [&](int st) {
        const uint32_t so = st * STG;
#pragma unroll
        for (int ks = 0; ks < 2; ks++) {
            uint32_t ah[2][4], al[2][4], bf[8][2];
            ldmx4(ah[0], a_base[0] + so + ks * 32);
            ldmx4(ah[1], a_base[1] + so + ks * 32);
            ldmx4(al[0], a_base[0] + so + (AL - AH) + ks * 32);
            ldmx4(al[1], a_base[1] + so + (AL - AH) + ks * 32);
#pragma unroll
            for (int p = 0; p < 4; p++) {
                uint32_t r[4];
                ldmx4(r, b_base[p] + so + ks * 32);
                bf[2 * p][0] = r[0]; bf[2 * p][1] = r[1];
                bf[2 * p + 1][0] = r[2]; bf[2 * p + 1][1] = r[3];
            }
#pragma unroll
            for (int mt = 0; mt < 2; mt++)
#pragma unroll
                for (int nt = 0; nt < 8; nt++) mma_bf16(acc[mt][nt], ah[mt], bf[nt]);
#pragma unroll
            for (int mt = 0; mt < 2; mt++)
#pragma unroll
                for (int nt = 0; nt < 8; nt++) mma_bf16(acc[mt][nt], al[mt], bf[nt]);
#pragma unroll
            for (int p = 0; p < 4; p++) {
                uint32_t r[4];
                ldmx4(r, b_base[p] + so + (BLo - BHo) + ks * 32);
                bf[2 * p][0] = r[0]; bf[2 * p][1] = r[1];
                bf[2 * p + 1][0] = r[2]; bf[2 * p + 1][1] = r[3];
            }
#pragma unroll
            for (int mt = 0; mt < 2; mt++)
#pragma unroll
                for (int nt = 0; nt < 8; nt++) mma_bf16(acc[mt][nt], ah[mt], bf[nt]);
        }
    };

    // prologue
    cpa(0, 0);
    ldgA(0);
    stsA(0);
    cp_wait0();
    __syncthreads();

    int cur = 0;
    for (int it = 1; it < NIT; it++) {
        cpa(it, cur ^ 1);      // async loads retire under compute
        ldgA(it);
        compute(cur);
        stsA(cur ^ 1);
        cp_wait0();
        __syncthreads();
        cur ^= 1;
    }
    compute(cur);

    // direct-register epilogue
#pragma unroll
    for (int mt = 0; mt < 2; mt++) {
        int r0 = wm + mt * 16 + (lane >> 2);
        int gm0 = m0 + r0;
        int gm1 = gm0 + 8;
        float s0 = (gm0 < M) ? g_dinv[gm0] : 0.0f;
        float s1 = (gm1 < M) ? g_dinv[gm1] : 0.0f;
#pragma unroll
        for (int nt = 0; nt < 8; nt++) {
            int col = n0 + wn + nt * 8 + (lane & 3) * 2;
            if (gm0 < M)
                *(float2*)&C0[(size_t)gm0 * N + col] =
                    make_float2(acc[mt][nt][0] * s0, acc[mt][nt][1] * s0);
            if (gm1 < M)
                *(float2*)&C0[(size_t)gm1 * N + col] =
                    make_float2(acc[mt][nt][2] * s1, acc[mt][nt][3] * s1);
        }
    }
}

// -------------------- fused gather-aggregate + bias (+relu/split) ----------
template <int LAYER>
__global__ void k_gather(const float* __restrict__ bias, float* __restrict__ out_param) {
    constexpr int NC = (LAYER == 1) ? HH : DOUT;
    constexpr int CH = NC / 4;
    const float* __restrict__ hs = (LAYER == 1) ? g_hs1 : g_hs2;

    int gtid = blockIdx.x * blockDim.x + threadIdx.x;
    int node = gtid / CH;
    if (node >= NN) return;
    int c = (gtid % CH) * 4;

    float4 v = *(const float4*)&hs[(size_t)node * NC + c];   // self loop
    int beg = g_ptr[node];
    int end = beg + g_cnt[node];
    int j = beg;
    for (; j + 1 < end; j += 2) {
        int s0 = g_csr[j], s1 = g_csr[j + 1];
        float4 a = *(const float4*)&hs[(size_t)s0 * NC + c];
        float4 b = *(const float4*)&hs[(size_t)s1 * NC + c];
        v.x += a.x + b.x; v.y += a.y + b.y; v.z += a.z + b.z; v.w += a.w + b.w;
    }
    if (j < end) {
        int s0 = g_csr[j];
        float4 a = *(const float4*)&hs[(size_t)s0 * NC + c];
        v.x += a.x; v.y += a.y; v.z += a.z; v.w += a.w;
    }

    float s = g_dinv[node];
    float4 b = *(const float4*)&bias[c];
    float4 r = make_float4(fmaf(v.x, s, b.x), fmaf(v.y, s, b.y),
                           fmaf(v.z, s, b.z), fmaf(v.w, s, b.w));
    if (LAYER == 1) {
        r.x = fmaxf(r.x, 0.f); r.y = fmaxf(r.y, 0.f);
        r.z = fmaxf(r.z, 0.f); r.w = fmaxf(r.w, 0.f);
        unsigned short h0, h1, h2, h3, l0, l1, l2, l3;
        split_bf16(r.x, h0, l0); split_bf16(r.y, h1, l1);
        split_bf16(r.z, h2, l2); split_bf16(r.w, h3, l3);
        uint2 uh = make_uint2((uint32_t)h0 | ((uint32_t)h1 << 16),
                              (uint32_t)h2 | ((uint32_t)h3 << 16));
        uint2 ul = make_uint2((uint32_t)l0 | ((uint32_t)l1 << 16),
                              (uint32_t)l2 | ((uint32_t)l3 << 16));
        *(uint2*)((unsigned short*)g_h1h + (size_t)node * NC + c) = uh;
        *(uint2*)((unsigned short*)g_h1l + (size_t)node * NC + c) = ul;
    } else {
        *(float4*)&out_param[(size_t)node * NC + c] = r;
    }
}

// ---------------------------------------------------------------------------
extern "C" void kernel_launch(void* const* d_in, const int* in_sizes, int n_in,
                              void* d_out, int out_size) {
    const float* x  = (const float*)d_in[0];
    const void*  ei = d_in[1];
    const float* W1 = (const float*)d_in[2];
    const float* b1 = (const float*)d_in[3];
    const float* W2 = (const float*)d_in[4];
    const float* b2 = (const float*)d_in[5];
    float*       out = (float*)d_out;

    const int E = in_sizes[1] / 2;
    const int MB = (NN + 127) / 128;
    const int SMEM = 2 * 40960;
    const int PRE0_BLK = (FIN * HH + 255) / 256;     // 512 blocks covers all fused work

    cudaFuncSetAttribute(k_gemm_mma<1>, cudaFuncAttributeMaxDynamicSharedMemorySize, SMEM);
    cudaFuncSetAttribute(k_gemm_mma<2>, cudaFuncAttributeMaxDynamicSharedMemorySize, SMEM);

    // preproc: 3 launches, then GEMM1 is launch #4 (ncu capture window)
    k_pre0   <<<PRE0_BLK, 256>>>(ei, E, W1, W2);
    k_hist   <<<(E + 255) / 256, 256>>>(ei, E);
    k_ptrdinv<<<NBLK, 256>>>();

    // layer 1 (GEMM independent of CSR fill)
    k_gemm_mma<1><<<dim3(HH / 128, MB), 256, SMEM>>>(x);
    k_fill   <<<(E + 255) / 256, 256>>>(ei, E);
    k_gather<1><<<(NN * (HH / 4) + 255) / 256, 256>>>(b1, nullptr);
    // layer 2
    k_gemm_mma<2><<<dim3(DOUT / 128, MB), 256, SMEM>>>(nullptr);
    k_gather<2><<<(NN * (DOUT / 4) + 255) / 256, 256>>>(b2, out);
}